// round 12
// baseline (speedup 1.0000x reference)
#include <cuda_runtime.h>
#include <cuda_bf16.h>
#include <math.h>

#define NMAX 16000
#define EMAX 256000

// ---------------- static device scratch ----------------
__device__ float g_xvT [3*NMAX*64];
__device__ float g_f0  [NMAX*192];
__device__ float g_pre_s[NMAX*128];
__device__ float g_pre_v[3*NMAX*64];
__device__ float g_h1  [NMAX*192];
__device__ float g_g   [NMAX*192];
__device__ float g_xv2T[3*NMAX*64];
__device__ float g_xs3 [NMAX*128];
__device__ float g_xv3 [3*NMAX*64];
__device__ float g_ns  [NMAX*192];
__device__ float g_nv  [3*NMAX*192];
__device__ float g_nl1 [NMAX*32];
__device__ float g_Wl1c[128*32];
__device__ int   g_ei  [2*EMAX];
__device__ int   g_is64;

// ---------------- edge-index dtype detect/convert ----------------
__global__ void detect_kernel(const int* __restrict__ ei_raw) {
    if (threadIdx.x == 0 && blockIdx.x == 0) {
        int nz = 0;
        for (int i = 1; i < 256; i += 2) nz += (ei_raw[i] != 0);
        g_is64 = (nz == 0) ? 1 : 0;
    }
}
__global__ void convert_kernel(const int* __restrict__ ei_raw, int total) {
    int is64 = g_is64;
    for (int idx = blockIdx.x * blockDim.x + threadIdx.x; idx < total;
         idx += gridDim.x * blockDim.x)
        g_ei[idx] = is64 ? ei_raw[2 * idx] : ei_raw[idx];
}

// ---------------- prep ----------------
__global__ void prep_kernel(const float* __restrict__ x, int N) {
    int total = N * 192;
    for (int idx = blockIdx.x * blockDim.x + threadIdx.x; idx < total;
         idx += gridDim.x * blockDim.x) {
        int n = idx / 192, i = idx - n * 192;
        if (i < 128) {
            g_f0[n * 192 + i] = x[n * 320 + i];
        } else {
            int u = i - 128;
            float a = x[n * 320 + 128 + 3 * u + 0];
            float b = x[n * 320 + 128 + 3 * u + 1];
            float c = x[n * 320 + 128 + 3 * u + 2];
            g_xvT[(0 * N + n) * 64 + u] = a;
            g_xvT[(1 * N + n) * 64 + u] = b;
            g_xvT[(2 * N + n) * 64 + u] = c;
            g_f0[n * 192 + i] = sqrtf(a * a + b * b + c * c + 1e-12f);
        }
    }
}

__global__ void gate_kernel(int N) {
    int total = 3 * N * 64;
    for (int idx = blockIdx.x * blockDim.x + threadIdx.x; idx < total;
         idx += gridDim.x * blockDim.x) {
        int rem = idx % (N * 64);
        int n = rem / 64, u = rem - n * 64;
        g_xv2T[idx] = g_xvT[idx] * g_g[n * 192 + 128 + u];
    }
}

__global__ void zero_kernel(int N) {
    int t1 = N * 192, t2 = 3 * N * 192, total = t1 + t2;
    for (int idx = blockIdx.x * blockDim.x + threadIdx.x; idx < total;
         idx += gridDim.x * blockDim.x) {
        if (idx < t1) g_ns[idx] = 0.f;
        else          g_nv[idx - t1] = 0.f;
    }
}

__global__ void wsum_kernel(const float* __restrict__ Wl1) {
    int idx = blockIdx.x * blockDim.x + threadIdx.x;
    if (idx < 128 * 32) g_Wl1c[idx] = Wl1[idx] + Wl1[128 * 32 + idx];
}

__global__ void nl1_kernel(int N) {
    __shared__ float sW[128 * 32];
    int tid = threadIdx.x;
    for (int i = tid; i < 128 * 32; i += 256) sW[i] = g_Wl1c[i];
    __syncthreads();
    int j = tid & 31;
    int n = blockIdx.x * 8 + (tid >> 5);
    if (n >= N) return;
    const float* row = &g_pre_s[(size_t)n * 128];
    float acc = 0.f;
#pragma unroll 8
    for (int q = 0; q < 128; q++) acc += row[q] * sW[q * 32 + j];
    g_nl1[(size_t)n * 32 + j] = acc;
}

// ---------------- multi-job SGEMM, flat 1D grid (round-9 proven) ----------------
struct GemmJob {
    const float* X; const float* W; float* C; const float* bias;
    int ldx, ldw, ldc;
    int K;
    float scale;
    int act, out_mode, nnodes;
    int gx, gy, off;
};

__device__ __forceinline__ void gemm_body(const GemmJob& jb, int bx, int by) {
    __shared__ __align__(16) float sX[2][16][132];
    __shared__ __align__(16) float sW[2][16][68];
    int bm = by * 128, bo = bx * 64;
    int tid = threadIdx.x;
    int tr = tid >> 4, tc = tid & 15;
    int m0 = tr * 8, o0 = tc * 4;

    float acc[8][4];
#pragma unroll
    for (int i = 0; i < 8; i++)
#pragma unroll
        for (int j = 0; j < 4; j++) acc[i][j] = 0.f;

    int xr[8], xc[8];
#pragma unroll
    for (int l = 0; l < 8; l++) {
        int i = tid + l * 256;
        xr[l] = i >> 4; xc[l] = i & 15;
    }
    int wr[4], wc[4];
#pragma unroll
    for (int l = 0; l < 4; l++) {
        int i = tid + l * 256;
        wr[l] = i >> 6; wc[l] = i & 63;
    }

    int ntiles = jb.K >> 4;
    float rx[8], rw[4];
#pragma unroll
    for (int l = 0; l < 8; l++)
        rx[l] = jb.X[(long long)(bm + xr[l]) * jb.ldx + xc[l]];
#pragma unroll
    for (int l = 0; l < 4; l++)
        rw[l] = jb.W[(long long)wr[l] * jb.ldw + bo + wc[l]];

    for (int t = 0; t < ntiles; t++) {
        int buf = t & 1;
#pragma unroll
        for (int l = 0; l < 8; l++) sX[buf][xc[l]][xr[l]] = rx[l];
#pragma unroll
        for (int l = 0; l < 4; l++) sW[buf][wr[l]][wc[l]] = rw[l];
        __syncthreads();
        if (t + 1 < ntiles) {
            int k0 = (t + 1) << 4;
#pragma unroll
            for (int l = 0; l < 8; l++)
                rx[l] = jb.X[(long long)(bm + xr[l]) * jb.ldx + k0 + xc[l]];
#pragma unroll
            for (int l = 0; l < 4; l++)
                rw[l] = jb.W[(long long)(k0 + wr[l]) * jb.ldw + bo + wc[l]];
        }
#pragma unroll
        for (int k = 0; k < 16; k++) {
            float4 a0 = *reinterpret_cast<const float4*>(&sX[buf][k][m0]);
            float4 a1 = *reinterpret_cast<const float4*>(&sX[buf][k][m0 + 4]);
            float4 b  = *reinterpret_cast<const float4*>(&sW[buf][k][o0]);
            float av[8] = {a0.x, a0.y, a0.z, a0.w, a1.x, a1.y, a1.z, a1.w};
            float bv[4] = {b.x, b.y, b.z, b.w};
#pragma unroll
            for (int i = 0; i < 8; i++)
#pragma unroll
                for (int j = 0; j < 4; j++) acc[i][j] += av[i] * bv[j];
        }
        __syncthreads();
    }

#pragma unroll
    for (int i = 0; i < 8; i++) {
        int m = bm + m0 + i;
#pragma unroll
        for (int j = 0; j < 4; j++) {
            int o = bo + o0 + j;
            float v = acc[i][j] * jb.scale;
            if (jb.bias) v += jb.bias[o];
            if (jb.act == 1) v = v / (1.f + expf(-v));
            if (jb.out_mode == 0) {
                jb.C[(long long)m * jb.ldc + o] = v;
            } else {
                int cc = m / jb.nnodes;
                int n = m - cc * jb.nnodes;
                jb.C[(long long)n * 640 + 256 + o * 3 + cc] = v;
            }
        }
    }
}

__global__ void __launch_bounds__(256)
gemm_multi(GemmJob j0, GemmJob j1, GemmJob j2) {
    int b = blockIdx.x;
    GemmJob jb = (b >= j2.off) ? j2 : (b >= j1.off) ? j1 : j0;
    int local = b - jb.off;
    gemm_body(jb, local % jb.gx, local / jb.gx);
}

// ---------------- helpers ----------------
__device__ __forceinline__ void red2(float* addr, float a, float b) {
    asm volatile("red.global.add.v2.f32 [%0], {%1,%2};"
                 :: "l"(addr), "f"(a), "f"(b) : "memory");
}
__device__ __forceinline__ float ssp_f(float x) {
    const float ln2 = 0.69314718055994531f;
    return fmaxf(x, 0.f) + log1pf(expf(-fabsf(x))) - ln2;
}
__device__ __forceinline__ void ldsm_x4(unsigned* r, unsigned addr) {
    asm volatile("ldmatrix.sync.aligned.m8n8.x4.shared.b16 {%0,%1,%2,%3}, [%4];"
                 : "=r"(r[0]), "=r"(r[1]), "=r"(r[2]), "=r"(r[3]) : "r"(addr));
}
__device__ __forceinline__ void ldsm_x2t(unsigned* r, unsigned addr) {
    asm volatile("ldmatrix.sync.aligned.m8n8.x2.trans.shared.b16 {%0,%1}, [%2];"
                 : "=r"(r[0]), "=r"(r[1]) : "r"(addr));
}
__device__ __forceinline__ void mma_bf16(float* d, const unsigned* a, const unsigned* b) {
    asm volatile("mma.sync.aligned.m16n8k16.row.col.f32.bf16.bf16.f32 "
                 "{%0,%1,%2,%3}, {%4,%5,%6,%7}, {%8,%9}, {%0,%1,%2,%3};"
                 : "+f"(d[0]), "+f"(d[1]), "+f"(d[2]), "+f"(d[3])
                 : "r"(a[0]), "r"(a[1]), "r"(a[2]), "r"(a[3]), "r"(b[0]), "r"(b[1]));
}
__device__ __forceinline__ void split_bf16(float v, __nv_bfloat16& hi, __nv_bfloat16& lo) {
    hi = __float2bfloat16(v);
    lo = __float2bfloat16(v - __bfloat162float(hi));
}

// ---------------- fused edge kernel v6: tensor-core layer-2 ----------------
#define ETILE 96
#define ETHREADS 384
// float offsets — bf16 weight region = 4 arrays * 12288 bf16 = 49152 bf16 = 24576 floats
#define OFF_WF1 0
#define OFF_WC  (OFF_WF1 + 1024)
#define OFF_BW  (OFF_WC + 2048)
#define OFF_EA  (OFF_BW + 24576)       // sea 96*33
#define OFF_NL  (OFF_EA + 96*33)       // snl 96*33
#define OFF_IP  (OFF_NL + 96*33)       // sip 96*65  (overlaid by bH arrays after transpose)
#define OFF_EAT (OFF_IP + 96*65)       // seaT 32*96
#define OFF_IPT (OFF_EAT + 32*96)      // sipT 64*96
#define OFF_SH  (OFF_IPT + 64*96)      // ssh 384
#define OFF_END (OFF_SH + 384)
#define EDGE_SMEM_BYTES (OFF_END*4 + 192*4)

__global__ void __launch_bounds__(ETHREADS, 1)
edge_kernel(const float* __restrict__ edge_attr,
            const float* __restrict__ edge_sh,
            const float* __restrict__ Wf1, const float* __restrict__ Wf2,
            const float* __restrict__ Wl1, const float* __restrict__ Wl2,
            int E, int N) {
    extern __shared__ float sm[];
    float* sWf1 = sm + OFF_WF1;
    float* sWc  = sm + OFF_WC;
    __nv_bfloat16* bW = (__nv_bfloat16*)(sm + OFF_BW);
    __nv_bfloat16* bWf2h = bW;
    __nv_bfloat16* bWf2l = bW + 12288;
    __nv_bfloat16* bWl2h = bW + 24576;
    __nv_bfloat16* bWl2l = bW + 36864;
    float* sea  = sm + OFF_EA;
    float* snl  = sm + OFF_NL;
    float* sip  = sm + OFF_IP;
    __nv_bfloat16* bH = (__nv_bfloat16*)(sm + OFF_IP);   // overlay (sip dead after transpose)
    __nv_bfloat16* bHfh = bH;
    __nv_bfloat16* bHfl = bH + 3072;
    __nv_bfloat16* bHlh = bH + 6144;
    __nv_bfloat16* bHll = bH + 9216;
    float* seaT = sm + OFF_EAT;
    float* sipT = sm + OFF_IPT;
    float* ssh  = sm + OFF_SH;
    int*   sidx = (int*)(sm + OFF_END);

    int tid = threadIdx.x;
    int warp = tid >> 5, lane = tid & 31;

    // stage fp32 MLP-1 weights + bf16 hi/lo layer-2 weights (once)
    for (int i = tid; i < 1024; i += ETHREADS) sWf1[i] = Wf1[i];
    for (int i = tid; i < 2048; i += ETHREADS) sWc[i]  = Wl1[256 * 32 + i];
    for (int i = tid; i < 12288; i += ETHREADS) {
        __nv_bfloat16 hi, lo;
        split_bf16(Wf2[i], hi, lo);
        bWf2h[i] = hi; bWf2l[i] = lo;
        split_bf16(Wl2[i], hi, lo);
        bWl2h[i] = hi; bWl2l[i] = lo;
    }

    const float c0 = 0.5f, c1 = 0.86602540378443865f;
    const float inv3 = 1.f / 3.f;
    const float inv32 = 0.03125f;
    const float invs32 = 0.17677669529663687f;
    const float invs320 = 0.05590169943749474f;
    const float invs3 = 0.57735026918962576f;

    // mma tiling: 12 warps = 6 mtiles x 2 nt-halves
    int mt = warp >> 1;
    int t0 = mt * 16;
    int g = lane >> 2, tg = lane & 3;
    int arow = t0 + (lane & 15);
    int acolh = (lane >> 4) << 3;

    int ntiles_e = (E + ETILE - 1) / ETILE;
    for (int tile = blockIdx.x; tile < ntiles_e; tile += gridDim.x) {
        int e0 = tile * ETILE;
        int cnt = min(ETILE, E - e0);
        __syncthreads();   // smem reuse fence

        if (tid < ETILE) {
            int valid = tid < cnt;
            sidx[tid]         = valid ? g_ei[e0 + tid]     : 0;
            sidx[ETILE + tid] = valid ? g_ei[E + e0 + tid] : 0;
        }
        if (tid < ETILE * 4) {
            int t = tid >> 2, q = tid & 3;
            ssh[tid] = (t < cnt) ? edge_sh[(size_t)(e0 + t) * 4 + q] : 0.f;
        }
        for (int i = tid; i < ETILE * 32; i += ETHREADS) {
            int t = i >> 5, q = i & 31;
            sea[t * 33 + q] = (t < cnt) ? edge_attr[(size_t)(e0 + t) * 32 + q] : 0.f;
        }
        __syncthreads();

        // gather: sip[t][u], snl[t][j]
#pragma unroll 2
        for (int i = tid; i < ETILE * 64; i += ETHREADS) {
            int t = i >> 6, u = i & 63;
            int d = sidx[t], s = sidx[ETILE + t];
            float acc = 0.f;
#pragma unroll
            for (int c = 0; c < 3; c++)
                acc += g_pre_v[((size_t)c * N + d) * 64 + u] *
                       g_pre_v[((size_t)c * N + s) * 64 + u];
            sip[t * 65 + u] = acc * inv3;
        }
        for (int i = tid; i < ETILE * 32; i += ETHREADS) {
            int t = i >> 5, j = i & 31;
            snl[t * 33 + j] = g_nl1[(size_t)sidx[t] * 32 + j];
        }
        __syncthreads();

        // transpose: seaT[q][t], sipT[u][t]
        for (int i = tid; i < 32 * ETILE; i += ETHREADS) {
            int t = i % ETILE, q = i / ETILE;
            seaT[q * ETILE + t] = sea[t * 33 + q];
        }
        for (int i = tid; i < 64 * ETILE; i += ETHREADS) {
            int t = i % ETILE, u = i / ETILE;
            sipT[u * ETILE + t] = sip[t * 65 + u];
        }
        __syncthreads();   // sip now dead -> bH overlay

        // MLP-1: hf then hl, write bf16 hi/lo [t][j]
        {
            int tt0 = (tid % 48) * 2, j0 = (tid / 48) * 4;
            float acc[2][4];
#pragma unroll
            for (int a = 0; a < 2; a++)
#pragma unroll
                for (int b = 0; b < 4; b++) acc[a][b] = 0.f;
#pragma unroll 4
            for (int q = 0; q < 32; q++) {
                float2 hv = *reinterpret_cast<const float2*>(&seaT[q * ETILE + tt0]);
                float4 wv = *reinterpret_cast<const float4*>(&sWf1[q * 32 + j0]);
                float h[2] = {hv.x, hv.y};
                float w[4] = {wv.x, wv.y, wv.z, wv.w};
#pragma unroll
                for (int a = 0; a < 2; a++)
#pragma unroll
                    for (int b = 0; b < 4; b++) acc[a][b] += h[a] * w[b];
            }
#pragma unroll
            for (int a = 0; a < 2; a++) {
#pragma unroll
                for (int b = 0; b < 4; b++) {
                    float v = ssp_f(acc[a][b] * invs32);
                    __nv_bfloat16 hi, lo;
                    split_bf16(v, hi, lo);
                    bHfh[(tt0 + a) * 32 + j0 + b] = hi;
                    bHfl[(tt0 + a) * 32 + j0 + b] = lo;
                }
            }
#pragma unroll
            for (int a = 0; a < 2; a++)
#pragma unroll
                for (int b = 0; b < 4; b++) acc[a][b] = snl[(tt0 + a) * 33 + j0 + b];
#pragma unroll 4
            for (int u = 0; u < 64; u++) {
                float2 hv = *reinterpret_cast<const float2*>(&sipT[u * ETILE + tt0]);
                float4 wv = *reinterpret_cast<const float4*>(&sWc[u * 32 + j0]);
                float h[2] = {hv.x, hv.y};
                float w[4] = {wv.x, wv.y, wv.z, wv.w};
#pragma unroll
                for (int a = 0; a < 2; a++)
#pragma unroll
                    for (int b = 0; b < 4; b++) acc[a][b] += h[a] * w[b];
            }
#pragma unroll
            for (int a = 0; a < 2; a++) {
#pragma unroll
                for (int b = 0; b < 4; b++) {
                    float v = ssp_f(acc[a][b] * invs320);
                    __nv_bfloat16 hi, lo;
                    split_bf16(v, hi, lo);
                    bHlh[(tt0 + a) * 32 + j0 + b] = hi;
                    bHll[(tt0 + a) * 32 + j0 + b] = lo;
                }
            }
        }
        __syncthreads();

        // ---- layer 2 via mma.sync (bf16 split) ----
        unsigned Af[2][2][2][4];
        {
            const __nv_bfloat16* hsrc[2][2] = {{bHfh, bHfl}, {bHlh, bHll}};
#pragma unroll
            for (int h = 0; h < 2; h++)
#pragma unroll
                for (int p = 0; p < 2; p++)
#pragma unroll
                    for (int k = 0; k < 2; k++) {
                        unsigned addr = (unsigned)__cvta_generic_to_shared(
                            hsrc[h][p] + arow * 32 + acolh + k * 16);
                        ldsm_x4(Af[h][p][k], addr);
                    }
        }

        int ta = t0 + g, tb = ta + 8;
        int da = sidx[ta], sa = sidx[ETILE + ta];
        int db = sidx[tb], sb = sidx[ETILE + tb];
        float4 shA = *reinterpret_cast<const float4*>(&ssh[ta * 4]);
        float4 shB = *reinterpret_cast<const float4*>(&ssh[tb * 4]);
        bool va = ta < cnt, vb = tb < cnt;
        int brow = lane & 15;

        for (int nt = (warp & 1); nt < 48; nt += 2) {
            int o0 = nt * 8;
            unsigned Bf[2][2][2][2];
            const __nv_bfloat16* wsrc[2][2] = {{bWf2h, bWf2l}, {bWl2h, bWl2l}};
#pragma unroll
            for (int w = 0; w < 2; w++)
#pragma unroll
                for (int p = 0; p < 2; p++)
#pragma unroll
                    for (int k = 0; k < 2; k++) {
                        unsigned addr = (unsigned)__cvta_generic_to_shared(
                            wsrc[w][p] + (k * 16 + brow) * 384 + o0);
                        ldsm_x2t(Bf[w][p][k], addr);
                    }

            float df[4] = {0.f, 0.f, 0.f, 0.f};
            float dl[4] = {0.f, 0.f, 0.f, 0.f};
#pragma unroll
            for (int k = 0; k < 2; k++) {
                mma_bf16(df, Af[0][0][k], Bf[0][0][k]);
                mma_bf16(df, Af[0][0][k], Bf[0][1][k]);
                mma_bf16(df, Af[0][1][k], Bf[0][0][k]);
                mma_bf16(dl, Af[1][0][k], Bf[1][0][k]);
                mma_bf16(dl, Af[1][0][k], Bf[1][1][k]);
                mma_bf16(dl, Af[1][1][k], Bf[1][0][k]);
            }

            int o = o0 + tg * 2;
            float wa0 = df[0] * dl[0] * inv32, wa1 = df[1] * dl[1] * inv32;
            float wb0 = df[2] * dl[2] * inv32, wb1 = df[3] * dl[3] * inv32;

            if (o0 < 128) {
                if (va) {
                    float2 hs = *reinterpret_cast<const float2*>(&g_xs3[(size_t)sa * 128 + o]);
                    float k = c0 * shA.x;
                    red2(&g_ns[(size_t)da * 192 + o], k * wa0 * hs.x, k * wa1 * hs.y);
                }
                if (vb) {
                    float2 hs = *reinterpret_cast<const float2*>(&g_xs3[(size_t)sb * 128 + o]);
                    float k = c0 * shB.x;
                    red2(&g_ns[(size_t)db * 192 + o], k * wb0 * hs.x, k * wb1 * hs.y);
                }
            } else if (o0 < 256) {
                int u = o - 128;
                if (va) {
                    float2 hs = *reinterpret_cast<const float2*>(&g_xs3[(size_t)sa * 128 + u]);
                    float b0 = c1 * wa0 * hs.x, b1 = c1 * wa1 * hs.y;
                    float shc[3] = {shA.y, shA.z, shA.w};
#pragma unroll
                    for (int c = 0; c < 3; c++)
                        red2(&g_nv[((size_t)c * N + da) * 192 + u], b0 * shc[c], b1 * shc[c]);
                }
                if (vb) {
                    float2 hs = *reinterpret_cast<const float2*>(&g_xs3[(size_t)sb * 128 + u]);
                    float b0 = c1 * wb0 * hs.x, b1 = c1 * wb1 * hs.y;
                    float shc[3] = {shB.y, shB.z, shB.w};
#pragma unroll
                    for (int c = 0; c < 3; c++)
                        red2(&g_nv[((size_t)c * N + db) * 192 + u], b0 * shc[c], b1 * shc[c]);
                }
            } else if (o0 < 320) {
                int u = o - 256;
                if (va) {
                    float b0 = c1 * wa0 * shA.x, b1 = c1 * wa1 * shA.x;
#pragma unroll
                    for (int c = 0; c < 3; c++) {
                        float2 hv = *reinterpret_cast<const float2*>(
                            &g_xv3[((size_t)c * N + sa) * 64 + u]);
                        red2(&g_nv[((size_t)c * N + da) * 192 + 128 + u], b0 * hv.x, b1 * hv.y);
                    }
                }
                if (vb) {
                    float b0 = c1 * wb0 * shB.x, b1 = c1 * wb1 * shB.x;
#pragma unroll
                    for (int c = 0; c < 3; c++) {
                        float2 hv = *reinterpret_cast<const float2*>(
                            &g_xv3[((size_t)c * N + sb) * 64 + u]);
                        red2(&g_nv[((size_t)c * N + db) * 192 + 128 + u], b0 * hv.x, b1 * hv.y);
                    }
                }
            } else {
                int u = o - 320;
                float k = c0 * invs3;
                if (va) {
                    float2 hx = *reinterpret_cast<const float2*>(&g_xv3[((size_t)0 * N + sa) * 64 + u]);
                    float2 hy = *reinterpret_cast<const float2*>(&g_xv3[((size_t)1 * N + sa) * 64 + u]);
                    float2 hz = *reinterpret_cast<const float2*>(&g_xv3[((size_t)2 * N + sa) * 64 + u]);
                    red2(&g_ns[(size_t)da * 192 + 128 + u],
                         k * wa0 * (hx.x * shA.y + hy.x * shA.z + hz.x * shA.w),
                         k * wa1 * (hx.y * shA.y + hy.y * shA.z + hz.y * shA.w));
                }
                if (vb) {
                    float2 hx = *reinterpret_cast<const float2*>(&g_xv3[((size_t)0 * N + sb) * 64 + u]);
                    float2 hy = *reinterpret_cast<const float2*>(&g_xv3[((size_t)1 * N + sb) * 64 + u]);
                    float2 hz = *reinterpret_cast<const float2*>(&g_xv3[((size_t)2 * N + sb) * 64 + u]);
                    red2(&g_ns[(size_t)db * 192 + 128 + u],
                         k * wb0 * (hx.x * shB.y + hy.x * shB.z + hz.x * shB.w),
                         k * wb1 * (hx.y * shB.y + hy.y * shB.z + hz.y * shB.w));
                }
            }
        }
    }
}

// ---------------- launch ----------------
static GemmJob mkjob(const float* X, int ldx, const float* W, int ldw,
                     float* C, int ldc, int M, int K, int O,
                     float scale, const float* bias, int act,
                     int out_mode, int nnodes, int off) {
    GemmJob j;
    j.X = X; j.W = W; j.C = C; j.bias = bias;
    j.ldx = ldx; j.ldw = ldw; j.ldc = ldc;
    j.K = K; j.scale = scale; j.act = act;
    j.out_mode = out_mode; j.nnodes = nnodes;
    j.gx = O / 64; j.gy = M / 128; j.off = off;
    return j;
}

extern "C" void kernel_launch(void* const* d_in, const int* in_sizes, int n_in,
                              void* d_out, int out_size) {
    const float* x      = (const float*)d_in[0];
    const int*   ei_raw = (const int*)d_in[1];
    const float* ea     = (const float*)d_in[2];
    const float* esh    = (const float*)d_in[3];
    const float* Wpre_s = (const float*)d_in[4];
    const float* bpre_s = (const float*)d_in[5];
    const float* Wpre_v = (const float*)d_in[6];
    const float* Wg1    = (const float*)d_in[7];
    const float* bg1    = (const float*)d_in[8];
    const float* Wg2    = (const float*)d_in[9];
    const float* bg2    = (const float*)d_in[10];
    const float* Wn_s   = (const float*)d_in[11];
    const float* bn_s   = (const float*)d_in[12];
    const float* Wn_v   = (const float*)d_in[13];
    const float* Wf1    = (const float*)d_in[14];
    const float* Wf2    = (const float*)d_in[15];
    const float* Wl1    = (const float*)d_in[16];
    const float* Wl2    = (const float*)d_in[17];
    const float* Wo_s   = (const float*)d_in[18];
    const float* bo_s   = (const float*)d_in[19];
    const float* Wo_v   = (const float*)d_in[20];

    int N = in_sizes[0] / 320;
    int E = in_sizes[1] / 2;
    float* out = (float*)d_out;

    float *p_xvT, *p_f0, *p_pre_s, *p_pre_v, *p_h1, *p_g, *p_xv2T, *p_xs3, *p_ns, *p_nv, *p_xv3;
    cudaGetSymbolAddress((void**)&p_xvT,  g_xvT);
    cudaGetSymbolAddress((void**)&p_f0,   g_f0);
    cudaGetSymbolAddress((void**)&p_pre_s,g_pre_s);
    cudaGetSymbolAddress((void**)&p_pre_v,g_pre_v);
    cudaGetSymbolAddress((void**)&p_h1,   g_h1);
    cudaGetSymbolAddress((void**)&p_g,    g_g);
    cudaGetSymbolAddress((void**)&p_xv2T, g_xv2T);
    cudaGetSymbolAddress((void**)&p_xs3,  g_xs3);
    cudaGetSymbolAddress((void**)&p_ns,   g_ns);
    cudaGetSymbolAddress((void**)&p_nv,   g_nv);
    cudaGetSymbolAddress((void**)&p_xv3,  g_xv3);

    const float s128 = 0.08838834764831845f;
    const float s64  = 0.125f;
    const float s192 = 0.07216878364870323f;

    detect_kernel<<<1, 32>>>(ei_raw);
    convert_kernel<<<512, 256>>>(ei_raw, 2 * E);
    prep_kernel<<<2048, 256>>>(x, N);

    // Phase A: pre_s | pre_v | h1
    {
        GemmJob jA = mkjob(x, 320, Wpre_s, 128, p_pre_s, 128, N, 128, 128, s128, bpre_s, 0, 0, 0, 0);
        int c0 = jA.gx * jA.gy;
        GemmJob jB = mkjob(p_xvT, 64, Wpre_v, 64, p_pre_v, 64, 3 * N, 64, 64, s64, nullptr, 0, 0, 0, c0);
        int c1 = c0 + jB.gx * jB.gy;
        GemmJob jC = mkjob(p_f0, 192, Wg1, 192, p_h1, 192, N, 192, 192, 1.f, bg1, 1, 0, 0, c1);
        int total = c1 + jC.gx * jC.gy;
        gemm_multi<<<total, 256>>>(jA, jB, jC);
    }
    // g = h1 @ Wg2 + bg2
    {
        GemmJob jA = mkjob(p_h1, 192, Wg2, 192, p_g, 192, N, 192, 192, 1.f, bg2, 0, 0, 0, 0);
        int total = jA.gx * jA.gy;
        GemmJob jX = jA; jX.off = total;
        gemm_multi<<<total, 256>>>(jA, jX, jX);
    }

    gate_kernel<<<2048, 256>>>(N);
    wsum_kernel<<<16, 256>>>(Wl1);
    nl1_kernel<<<(N + 7) / 8, 256>>>(N);

    // Phase B: xs3 (K=128) | xv3
    {
        GemmJob jA = mkjob(p_g, 192, Wn_s, 128, p_xs3, 128, N, 128, 128, s128, bn_s, 0, 0, 0, 0);
        int c0 = jA.gx * jA.gy;
        GemmJob jB = mkjob(p_xv2T, 64, Wn_v, 64, p_xv3, 64, 3 * N, 64, 64, s64, nullptr, 0, 0, 0, c0);
        int total = c0 + jB.gx * jB.gy;
        GemmJob jX = jB; jX.off = total;
        gemm_multi<<<total, 256>>>(jA, jB, jX);
    }

    zero_kernel<<<2048, 256>>>(N);

    cudaFuncSetAttribute(edge_kernel, cudaFuncAttributeMaxDynamicSharedMemorySize,
                         EDGE_SMEM_BYTES);
    edge_kernel<<<148, ETHREADS, EDGE_SMEM_BYTES>>>(ea, esh, Wf1, Wf2, Wl1, Wl2, E, N);

    // Phase C: outs | outv
    {
        GemmJob jA = mkjob(p_ns, 192, Wo_s, 256, out, 640, N, 192, 256, s192, bo_s, 0, 0, 0, 0);
        int c0 = jA.gx * jA.gy;
        GemmJob jB = mkjob(p_nv, 192, Wo_v, 128, out, 0, 3 * N, 192, 128, s192, nullptr, 0, 1, N, c0);
        int total = c0 + jB.gx * jB.gy;
        GemmJob jX = jB; jX.off = total;
        gemm_multi<<<total, 256>>>(jA, jB, jX);
    }
}

// round 13
// speedup vs baseline: 1.2550x; 1.2550x over previous
#include <cuda_runtime.h>
#include <math.h>

#define NMAX 16000
#define EMAX 256000

// ---------------- static device scratch ----------------
__device__ float g_xvT [3*NMAX*64];
__device__ float g_f0  [NMAX*192];
__device__ float g_pre_s[NMAX*128];
__device__ float g_pre_v[3*NMAX*64];
__device__ float g_h1  [NMAX*192];
__device__ float g_g   [NMAX*192];
__device__ float g_xv2T[3*NMAX*64];
__device__ float g_xs3 [NMAX*128];
__device__ float g_xv3 [3*NMAX*64];
__device__ float g_ns  [NMAX*192];
__device__ float g_nv  [3*NMAX*192];
__device__ float g_nl1 [NMAX*32];
__device__ float g_Wl1c[128*32];
__device__ int   g_ei  [2*EMAX];
__device__ int   g_perm[EMAX];
__device__ int   g_cnt [NMAX];
__device__ int   g_woff[NMAX];
__device__ int   g_is64;

// ---------------- edge-index dtype detect/convert ----------------
__global__ void detect_kernel(const int* __restrict__ ei_raw) {
    if (threadIdx.x == 0 && blockIdx.x == 0) {
        int nz = 0;
        for (int i = 1; i < 256; i += 2) nz += (ei_raw[i] != 0);
        g_is64 = (nz == 0) ? 1 : 0;
    }
}
__global__ void convert_kernel(const int* __restrict__ ei_raw, int total) {
    int is64 = g_is64;
    for (int idx = blockIdx.x * blockDim.x + threadIdx.x; idx < total;
         idx += gridDim.x * blockDim.x)
        g_ei[idx] = is64 ? ei_raw[2 * idx] : ei_raw[idx];
}

// ---------------- dst counting sort: zero/hist/scan/scatter ----------------
__global__ void zcnt_kernel(int N) {
    for (int i = blockIdx.x * blockDim.x + threadIdx.x; i < N;
         i += gridDim.x * blockDim.x) g_cnt[i] = 0;
}
__global__ void hist_kernel(int E) {
    for (int e = blockIdx.x * blockDim.x + threadIdx.x; e < E;
         e += gridDim.x * blockDim.x)
        atomicAdd(&g_cnt[g_ei[e]], 1);
}
__global__ void scan_kernel(int N) {
    __shared__ int bs[1024];
    int tid = threadIdx.x;
    int chunk = (N + 1023) / 1024;
    int base = tid * chunk;
    int s = 0;
    for (int i = 0; i < chunk; i++)
        if (base + i < N) s += g_cnt[base + i];
    bs[tid] = s;
    __syncthreads();
    if (tid == 0) {
        int r = 0;
        for (int i = 0; i < 1024; i++) { int t = bs[i]; bs[i] = r; r += t; }
    }
    __syncthreads();
    int run = bs[tid];
    for (int i = 0; i < chunk; i++) {
        if (base + i < N) {
            int c = g_cnt[base + i];
            g_woff[base + i] = run;
            run += c;
        }
    }
}
__global__ void scatter_kernel(int E) {
    for (int e = blockIdx.x * blockDim.x + threadIdx.x; e < E;
         e += gridDim.x * blockDim.x) {
        int d = g_ei[e];
        int pos = atomicAdd(&g_woff[d], 1);
        g_perm[pos] = e;
    }
}

// ---------------- prep ----------------
__global__ void prep_kernel(const float* __restrict__ x, int N) {
    int total = N * 192;
    for (int idx = blockIdx.x * blockDim.x + threadIdx.x; idx < total;
         idx += gridDim.x * blockDim.x) {
        int n = idx / 192, i = idx - n * 192;
        if (i < 128) {
            g_f0[n * 192 + i] = x[n * 320 + i];
        } else {
            int u = i - 128;
            float a = x[n * 320 + 128 + 3 * u + 0];
            float b = x[n * 320 + 128 + 3 * u + 1];
            float c = x[n * 320 + 128 + 3 * u + 2];
            g_xvT[(0 * N + n) * 64 + u] = a;
            g_xvT[(1 * N + n) * 64 + u] = b;
            g_xvT[(2 * N + n) * 64 + u] = c;
            g_f0[n * 192 + i] = sqrtf(a * a + b * b + c * c + 1e-12f);
        }
    }
}

__global__ void gate_kernel(int N) {
    int total = 3 * N * 64;
    for (int idx = blockIdx.x * blockDim.x + threadIdx.x; idx < total;
         idx += gridDim.x * blockDim.x) {
        int rem = idx % (N * 64);
        int n = rem / 64, u = rem - n * 64;
        g_xv2T[idx] = g_xvT[idx] * g_g[n * 192 + 128 + u];
    }
}

__global__ void zero_kernel(int N) {
    int t1 = N * 192, t2 = 3 * N * 192, total = t1 + t2;
    for (int idx = blockIdx.x * blockDim.x + threadIdx.x; idx < total;
         idx += gridDim.x * blockDim.x) {
        if (idx < t1) g_ns[idx] = 0.f;
        else          g_nv[idx - t1] = 0.f;
    }
}

__global__ void wsum_kernel(const float* __restrict__ Wl1) {
    int idx = blockIdx.x * blockDim.x + threadIdx.x;
    if (idx < 128 * 32) g_Wl1c[idx] = Wl1[idx] + Wl1[128 * 32 + idx];
}

__global__ void nl1_kernel(int N) {
    __shared__ float sW[128 * 32];
    int tid = threadIdx.x;
    for (int i = tid; i < 128 * 32; i += 256) sW[i] = g_Wl1c[i];
    __syncthreads();
    int j = tid & 31;
    int n = blockIdx.x * 8 + (tid >> 5);
    if (n >= N) return;
    const float* row = &g_pre_s[(size_t)n * 128];
    float acc = 0.f;
#pragma unroll 8
    for (int q = 0; q < 128; q++) acc += row[q] * sW[q * 32 + j];
    g_nl1[(size_t)n * 32 + j] = acc;
}

// ---------------- multi-job SGEMM, flat 1D grid (round-9 proven) ----------------
struct GemmJob {
    const float* X; const float* W; float* C; const float* bias;
    int ldx, ldw, ldc;
    int K;
    float scale;
    int act, out_mode, nnodes;
    int gx, gy, off;
};

__device__ __forceinline__ void gemm_body(const GemmJob& jb, int bx, int by) {
    __shared__ __align__(16) float sX[2][16][132];
    __shared__ __align__(16) float sW[2][16][68];
    int bm = by * 128, bo = bx * 64;
    int tid = threadIdx.x;
    int tr = tid >> 4, tc = tid & 15;
    int m0 = tr * 8, o0 = tc * 4;

    float acc[8][4];
#pragma unroll
    for (int i = 0; i < 8; i++)
#pragma unroll
        for (int j = 0; j < 4; j++) acc[i][j] = 0.f;

    int xr[8], xc[8];
#pragma unroll
    for (int l = 0; l < 8; l++) {
        int i = tid + l * 256;
        xr[l] = i >> 4; xc[l] = i & 15;
    }
    int wr[4], wc[4];
#pragma unroll
    for (int l = 0; l < 4; l++) {
        int i = tid + l * 256;
        wr[l] = i >> 6; wc[l] = i & 63;
    }

    int ntiles = jb.K >> 4;
    float rx[8], rw[4];
#pragma unroll
    for (int l = 0; l < 8; l++)
        rx[l] = jb.X[(long long)(bm + xr[l]) * jb.ldx + xc[l]];
#pragma unroll
    for (int l = 0; l < 4; l++)
        rw[l] = jb.W[(long long)wr[l] * jb.ldw + bo + wc[l]];

    for (int t = 0; t < ntiles; t++) {
        int buf = t & 1;
#pragma unroll
        for (int l = 0; l < 8; l++) sX[buf][xc[l]][xr[l]] = rx[l];
#pragma unroll
        for (int l = 0; l < 4; l++) sW[buf][wr[l]][wc[l]] = rw[l];
        __syncthreads();
        if (t + 1 < ntiles) {
            int k0 = (t + 1) << 4;
#pragma unroll
            for (int l = 0; l < 8; l++)
                rx[l] = jb.X[(long long)(bm + xr[l]) * jb.ldx + k0 + xc[l]];
#pragma unroll
            for (int l = 0; l < 4; l++)
                rw[l] = jb.W[(long long)(k0 + wr[l]) * jb.ldw + bo + wc[l]];
        }
#pragma unroll
        for (int k = 0; k < 16; k++) {
            float4 a0 = *reinterpret_cast<const float4*>(&sX[buf][k][m0]);
            float4 a1 = *reinterpret_cast<const float4*>(&sX[buf][k][m0 + 4]);
            float4 b  = *reinterpret_cast<const float4*>(&sW[buf][k][o0]);
            float av[8] = {a0.x, a0.y, a0.z, a0.w, a1.x, a1.y, a1.z, a1.w};
            float bv[4] = {b.x, b.y, b.z, b.w};
#pragma unroll
            for (int i = 0; i < 8; i++)
#pragma unroll
                for (int j = 0; j < 4; j++) acc[i][j] += av[i] * bv[j];
        }
        __syncthreads();
    }

#pragma unroll
    for (int i = 0; i < 8; i++) {
        int m = bm + m0 + i;
#pragma unroll
        for (int j = 0; j < 4; j++) {
            int o = bo + o0 + j;
            float v = acc[i][j] * jb.scale;
            if (jb.bias) v += jb.bias[o];
            if (jb.act == 1) v = v / (1.f + expf(-v));
            if (jb.out_mode == 0) {
                jb.C[(long long)m * jb.ldc + o] = v;
            } else {
                int cc = m / jb.nnodes;
                int n = m - cc * jb.nnodes;
                jb.C[(long long)n * 640 + 256 + o * 3 + cc] = v;
            }
        }
    }
}

__global__ void __launch_bounds__(256)
gemm_multi(GemmJob j0, GemmJob j1, GemmJob j2) {
    int b = blockIdx.x;
    GemmJob jb = (b >= j2.off) ? j2 : (b >= j1.off) ? j1 : j0;
    int local = b - jb.off;
    gemm_body(jb, local % jb.gx, local / jb.gx);
}

// ---------------- helpers ----------------
__device__ __forceinline__ void red4(float* addr, float a, float b, float c, float d) {
    asm volatile("red.global.add.v4.f32 [%0], {%1,%2,%3,%4};"
                 :: "l"(addr), "f"(a), "f"(b), "f"(c), "f"(d) : "memory");
}
__device__ __forceinline__ float ssp_f(float x) {
    const float ln2 = 0.69314718055994531f;
    return fmaxf(x, 0.f) + log1pf(expf(-fabsf(x))) - ln2;
}

// ---------------- fused edge kernel v7: sorted dst + register merge ----------------
#define ETILE 96
#define ETHREADS 768
#define OFF_WF1 0
#define OFF_WF2 (OFF_WF1 + 1024)
#define OFF_WC  (OFF_WF2 + 12288)
#define OFF_WL2 (OFF_WC + 2048)
#define OFF_EA  (OFF_WL2 + 12288)
#define OFF_NL  (OFF_EA + 96*33)
#define OFF_IP  (OFF_NL + 96*33)
#define OFF_EAT (OFF_IP + 96*65)
#define OFF_IPT (OFF_EAT + 32*96)
#define OFF_HF  (OFF_IPT + 64*96)
#define OFF_HL  (OFF_HF + 32*96)
#define OFF_SH  (OFF_HL + 32*96)
#define OFF_END (OFF_SH + 384)
#define EDGE_SMEM_BYTES (OFF_END*4 + 288*4)

__global__ void __launch_bounds__(ETHREADS, 1)
edge_kernel(const float* __restrict__ edge_attr,
            const float* __restrict__ edge_sh,
            const float* __restrict__ Wf1, const float* __restrict__ Wf2,
            const float* __restrict__ Wl1, const float* __restrict__ Wl2,
            int E, int N) {
    extern __shared__ float sm[];
    float* sWf1 = sm + OFF_WF1;
    float* sWf2 = sm + OFF_WF2;
    float* sWc  = sm + OFF_WC;
    float* sWl2 = sm + OFF_WL2;
    float* sea  = sm + OFF_EA;
    float* snl  = sm + OFF_NL;
    float* sip  = sm + OFF_IP;
    float* seaT = sm + OFF_EAT;
    float* sipT = sm + OFF_IPT;
    float* shfT = sm + OFF_HF;
    float* shlT = sm + OFF_HL;
    float* ssh  = sm + OFF_SH;
    int*   sidx = (int*)(sm + OFF_END);        // [0..95]=dst, [96..191]=src
    int*   seix = (int*)(sm + OFF_END) + 192;  // [0..95]=edge id

    int tid = threadIdx.x;
    for (int i = tid; i < 1024;  i += ETHREADS) sWf1[i] = Wf1[i];
    for (int i = tid; i < 12288; i += ETHREADS) sWf2[i] = Wf2[i];
    for (int i = tid; i < 2048;  i += ETHREADS) sWc[i]  = Wl1[256 * 32 + i];
    for (int i = tid; i < 12288; i += ETHREADS) sWl2[i] = Wl2[i];

    const float c0 = 0.5f, c1 = 0.86602540378443865f;
    const float inv3 = 1.f / 3.f;
    const float inv32 = 0.03125f;
    const float invs32 = 0.17677669529663687f;
    const float invs320 = 0.05590169943749474f;
    const float invs3 = 0.57735026918962576f;

    int warp = tid >> 5, lane = tid & 31;
    int eb = warp * 4;

    int ntiles = (E + ETILE - 1) / ETILE;
    for (int tile = blockIdx.x; tile < ntiles; tile += gridDim.x) {
        int e0 = tile * ETILE;
        int cnt = min(ETILE, E - e0);
        __syncthreads();   // smem reuse fence

        if (tid < ETILE) {
            int valid = tid < cnt;
            int e = valid ? g_perm[e0 + tid] : 0;
            seix[tid]         = e;
            sidx[tid]         = valid ? g_ei[e]     : -1;
            sidx[ETILE + tid] = valid ? g_ei[E + e] : 0;
        }
        __syncthreads();

        for (int i = tid; i < ETILE * 4; i += ETHREADS) {
            int t = i >> 2, q = i & 3;
            ssh[i] = (t < cnt) ? edge_sh[(size_t)seix[t] * 4 + q] : 0.f;
        }
        for (int i = tid; i < ETILE * 32; i += ETHREADS) {
            int t = i >> 5, q = i & 31;
            sea[t * 33 + q] = (t < cnt) ? edge_attr[(size_t)seix[t] * 32 + q] : 0.f;
        }
        // sip[t][u], snl[t][j]
        for (int i = tid; i < ETILE * 64; i += ETHREADS) {
            int t = i >> 6, u = i & 63;
            int valid = t < cnt;
            int d = valid ? sidx[t] : 0, s = sidx[ETILE + t];
            float acc = 0.f;
#pragma unroll
            for (int c = 0; c < 3; c++)
                acc += g_pre_v[((size_t)c * N + d) * 64 + u] *
                       g_pre_v[((size_t)c * N + s) * 64 + u];
            sip[t * 65 + u] = acc * inv3;
        }
        for (int i = tid; i < ETILE * 32; i += ETHREADS) {
            int t = i >> 5, j = i & 31;
            int d = (t < cnt) ? sidx[t] : 0;
            snl[t * 33 + j] = g_nl1[(size_t)d * 32 + j];
        }
        __syncthreads();

        // transpose
        for (int i = tid; i < 32 * ETILE; i += ETHREADS) {
            int t = i % ETILE, q = i / ETILE;
            seaT[q * ETILE + t] = sea[t * 33 + q];
        }
        for (int i = tid; i < 64 * ETILE; i += ETHREADS) {
            int t = i % ETILE, u = i / ETILE;
            sipT[u * ETILE + t] = sip[t * 65 + u];
        }
        __syncthreads();

        // MLP-1 register-blocked, warp-split
        if (warp < 6) {
            int idx = tid;
            int t0 = (idx % 24) * 4, j0 = (idx / 24) * 4;
            float acc[4][4];
#pragma unroll
            for (int a = 0; a < 4; a++)
#pragma unroll
                for (int b = 0; b < 4; b++) acc[a][b] = 0.f;
#pragma unroll 4
            for (int q = 0; q < 32; q++) {
                float4 hv = *reinterpret_cast<const float4*>(&seaT[q * ETILE + t0]);
                float4 wv = *reinterpret_cast<const float4*>(&sWf1[q * 32 + j0]);
                float h[4] = {hv.x, hv.y, hv.z, hv.w};
                float w[4] = {wv.x, wv.y, wv.z, wv.w};
#pragma unroll
                for (int a = 0; a < 4; a++)
#pragma unroll
                    for (int b = 0; b < 4; b++) acc[a][b] += h[a] * w[b];
            }
#pragma unroll
            for (int b = 0; b < 4; b++) {
                float4 o;
                o.x = ssp_f(acc[0][b] * invs32);
                o.y = ssp_f(acc[1][b] * invs32);
                o.z = ssp_f(acc[2][b] * invs32);
                o.w = ssp_f(acc[3][b] * invs32);
                *reinterpret_cast<float4*>(&shfT[(j0 + b) * ETILE + t0]) = o;
            }
        } else if (warp < 18) {
            int idx = tid - 192;
            int t0 = (idx % 48) * 2, j0 = (idx / 48) * 4;
            float acc[2][4];
#pragma unroll
            for (int a = 0; a < 2; a++)
#pragma unroll
                for (int b = 0; b < 4; b++) acc[a][b] = snl[(t0 + a) * 33 + j0 + b];
#pragma unroll 4
            for (int u = 0; u < 64; u++) {
                float2 hv = *reinterpret_cast<const float2*>(&sipT[u * ETILE + t0]);
                float4 wv = *reinterpret_cast<const float4*>(&sWc[u * 32 + j0]);
                float h[2] = {hv.x, hv.y};
                float w[4] = {wv.x, wv.y, wv.z, wv.w};
#pragma unroll
                for (int a = 0; a < 2; a++)
#pragma unroll
                    for (int b = 0; b < 4; b++) acc[a][b] += h[a] * w[b];
            }
#pragma unroll
            for (int b = 0; b < 4; b++) {
                float2 o;
                o.x = ssp_f(acc[0][b] * invs320);
                o.y = ssp_f(acc[1][b] * invs320);
                *reinterpret_cast<float2*>(&shlT[(j0 + b) * ETILE + t0]) = o;
            }
        }
        __syncthreads();

        // layer 2: per thread 4 edges x 4 outputs, dst-merged epilogue
#pragma unroll 1
        for (int ob = 0; ob < 3; ob++) {
            int o0 = ob * 128 + lane * 4;
            float wf[4][4], wl[4][4];
#pragma unroll
            for (int a = 0; a < 4; a++)
#pragma unroll
                for (int b = 0; b < 4; b++) { wf[a][b] = 0.f; wl[a][b] = 0.f; }

#pragma unroll 2
            for (int j = 0; j < 32; j++) {
                float4 hf = *reinterpret_cast<const float4*>(&shfT[j * ETILE + eb]);
                float4 hl = *reinterpret_cast<const float4*>(&shlT[j * ETILE + eb]);
                float4 af = *reinterpret_cast<const float4*>(&sWf2[j * 384 + o0]);
                float4 al = *reinterpret_cast<const float4*>(&sWl2[j * 384 + o0]);
                float hfv[4] = {hf.x, hf.y, hf.z, hf.w};
                float hlv[4] = {hl.x, hl.y, hl.z, hl.w};
                float afv[4] = {af.x, af.y, af.z, af.w};
                float alv[4] = {al.x, al.y, al.z, al.w};
#pragma unroll
                for (int a = 0; a < 4; a++)
#pragma unroll
                    for (int b = 0; b < 4; b++) {
                        wf[a][b] += hfv[a] * afv[b];
                        wl[a][b] += hlv[a] * alv[b];
                    }
            }

            // epilogue with same-dst register merging (edges sorted by dst)
            if (o0 < 128) {
                float A0 = 0, A1 = 0, A2 = 0, A3 = 0; int curd = -1;
#pragma unroll
                for (int a = 0; a < 4; a++) {
                    int t = eb + a;
                    if (t >= cnt) continue;
                    int d = sidx[t], s = sidx[ETILE + t];
                    float k = c0 * ssh[t * 4 + 0];
                    float4 hs = *reinterpret_cast<const float4*>(&g_xs3[(size_t)s * 128 + o0]);
                    float v0 = k * wf[a][0] * wl[a][0] * inv32 * hs.x;
                    float v1 = k * wf[a][1] * wl[a][1] * inv32 * hs.y;
                    float v2 = k * wf[a][2] * wl[a][2] * inv32 * hs.z;
                    float v3 = k * wf[a][3] * wl[a][3] * inv32 * hs.w;
                    if (d != curd) {
                        if (curd >= 0) red4(&g_ns[(size_t)curd * 192 + o0], A0, A1, A2, A3);
                        A0 = v0; A1 = v1; A2 = v2; A3 = v3; curd = d;
                    } else { A0 += v0; A1 += v1; A2 += v2; A3 += v3; }
                }
                if (curd >= 0) red4(&g_ns[(size_t)curd * 192 + o0], A0, A1, A2, A3);
            } else if (o0 < 256) {
                int u0 = o0 - 128;
                float A[3][4]; int curd = -1;
#pragma unroll
                for (int a = 0; a < 4; a++) {
                    int t = eb + a;
                    if (t >= cnt) continue;
                    int d = sidx[t], s = sidx[ETILE + t];
                    float4 hs = *reinterpret_cast<const float4*>(&g_xs3[(size_t)s * 128 + u0]);
                    float b0 = c1 * wf[a][0] * wl[a][0] * inv32 * hs.x;
                    float b1 = c1 * wf[a][1] * wl[a][1] * inv32 * hs.y;
                    float b2 = c1 * wf[a][2] * wl[a][2] * inv32 * hs.z;
                    float b3 = c1 * wf[a][3] * wl[a][3] * inv32 * hs.w;
                    if (d != curd) {
                        if (curd >= 0) {
#pragma unroll
                            for (int c = 0; c < 3; c++)
                                red4(&g_nv[((size_t)c * N + curd) * 192 + u0],
                                     A[c][0], A[c][1], A[c][2], A[c][3]);
                        }
#pragma unroll
                        for (int c = 0; c < 3; c++) {
                            float shc = ssh[t * 4 + 1 + c];
                            A[c][0] = b0 * shc; A[c][1] = b1 * shc;
                            A[c][2] = b2 * shc; A[c][3] = b3 * shc;
                        }
                        curd = d;
                    } else {
#pragma unroll
                        for (int c = 0; c < 3; c++) {
                            float shc = ssh[t * 4 + 1 + c];
                            A[c][0] += b0 * shc; A[c][1] += b1 * shc;
                            A[c][2] += b2 * shc; A[c][3] += b3 * shc;
                        }
                    }
                }
                if (curd >= 0) {
#pragma unroll
                    for (int c = 0; c < 3; c++)
                        red4(&g_nv[((size_t)c * N + curd) * 192 + u0],
                             A[c][0], A[c][1], A[c][2], A[c][3]);
                }
            } else if (o0 < 320) {
                int u0 = o0 - 256;
                float A[3][4]; int curd = -1;
#pragma unroll
                for (int a = 0; a < 4; a++) {
                    int t = eb + a;
                    if (t >= cnt) continue;
                    int d = sidx[t], s = sidx[ETILE + t];
                    float k0 = c1 * ssh[t * 4 + 0] * inv32;
                    float b0 = k0 * wf[a][0] * wl[a][0];
                    float b1 = k0 * wf[a][1] * wl[a][1];
                    float b2 = k0 * wf[a][2] * wl[a][2];
                    float b3 = k0 * wf[a][3] * wl[a][3];
                    if (d != curd) {
                        if (curd >= 0) {
#pragma unroll
                            for (int c = 0; c < 3; c++)
                                red4(&g_nv[((size_t)c * N + curd) * 192 + 128 + u0],
                                     A[c][0], A[c][1], A[c][2], A[c][3]);
                        }
#pragma unroll
                        for (int c = 0; c < 3; c++) {
                            float4 hv = *reinterpret_cast<const float4*>(
                                &g_xv3[((size_t)c * N + s) * 64 + u0]);
                            A[c][0] = b0 * hv.x; A[c][1] = b1 * hv.y;
                            A[c][2] = b2 * hv.z; A[c][3] = b3 * hv.w;
                        }
                        curd = d;
                    } else {
#pragma unroll
                        for (int c = 0; c < 3; c++) {
                            float4 hv = *reinterpret_cast<const float4*>(
                                &g_xv3[((size_t)c * N + s) * 64 + u0]);
                            A[c][0] += b0 * hv.x; A[c][1] += b1 * hv.y;
                            A[c][2] += b2 * hv.z; A[c][3] += b3 * hv.w;
                        }
                    }
                }
                if (curd >= 0) {
#pragma unroll
                    for (int c = 0; c < 3; c++)
                        red4(&g_nv[((size_t)c * N + curd) * 192 + 128 + u0],
                             A[c][0], A[c][1], A[c][2], A[c][3]);
                }
            } else {
                int u0 = o0 - 320;
                float A0 = 0, A1 = 0, A2 = 0, A3 = 0; int curd = -1;
#pragma unroll
                for (int a = 0; a < 4; a++) {
                    int t = eb + a;
                    if (t >= cnt) continue;
                    int d = sidx[t], s = sidx[ETILE + t];
                    float sh1 = ssh[t * 4 + 1], sh2v = ssh[t * 4 + 2], sh3 = ssh[t * 4 + 3];
                    float4 hx = *reinterpret_cast<const float4*>(&g_xv3[((size_t)0 * N + s) * 64 + u0]);
                    float4 hy = *reinterpret_cast<const float4*>(&g_xv3[((size_t)1 * N + s) * 64 + u0]);
                    float4 hz = *reinterpret_cast<const float4*>(&g_xv3[((size_t)2 * N + s) * 64 + u0]);
                    float k = c0 * invs3 * inv32;
                    float v0 = k * wf[a][0] * wl[a][0] * (hx.x * sh1 + hy.x * sh2v + hz.x * sh3);
                    float v1 = k * wf[a][1] * wl[a][1] * (hx.y * sh1 + hy.y * sh2v + hz.y * sh3);
                    float v2 = k * wf[a][2] * wl[a][2] * (hx.z * sh1 + hy.z * sh2v + hz.z * sh3);
                    float v3 = k * wf[a][3] * wl[a][3] * (hx.w * sh1 + hy.w * sh2v + hz.w * sh3);
                    if (d != curd) {
                        if (curd >= 0) red4(&g_ns[(size_t)curd * 192 + 128 + u0], A0, A1, A2, A3);
                        A0 = v0; A1 = v1; A2 = v2; A3 = v3; curd = d;
                    } else { A0 += v0; A1 += v1; A2 += v2; A3 += v3; }
                }
                if (curd >= 0) red4(&g_ns[(size_t)curd * 192 + 128 + u0], A0, A1, A2, A3);
            }
        }
    }
}

// ---------------- launch ----------------
static GemmJob mkjob(const float* X, int ldx, const float* W, int ldw,
                     float* C, int ldc, int M, int K, int O,
                     float scale, const float* bias, int act,
                     int out_mode, int nnodes, int off) {
    GemmJob j;
    j.X = X; j.W = W; j.C = C; j.bias = bias;
    j.ldx = ldx; j.ldw = ldw; j.ldc = ldc;
    j.K = K; j.scale = scale; j.act = act;
    j.out_mode = out_mode; j.nnodes = nnodes;
    j.gx = O / 64; j.gy = M / 128; j.off = off;
    return j;
}

extern "C" void kernel_launch(void* const* d_in, const int* in_sizes, int n_in,
                              void* d_out, int out_size) {
    const float* x      = (const float*)d_in[0];
    const int*   ei_raw = (const int*)d_in[1];
    const float* ea     = (const float*)d_in[2];
    const float* esh    = (const float*)d_in[3];
    const float* Wpre_s = (const float*)d_in[4];
    const float* bpre_s = (const float*)d_in[5];
    const float* Wpre_v = (const float*)d_in[6];
    const float* Wg1    = (const float*)d_in[7];
    const float* bg1    = (const float*)d_in[8];
    const float* Wg2    = (const float*)d_in[9];
    const float* bg2    = (const float*)d_in[10];
    const float* Wn_s   = (const float*)d_in[11];
    const float* bn_s   = (const float*)d_in[12];
    const float* Wn_v   = (const float*)d_in[13];
    const float* Wf1    = (const float*)d_in[14];
    const float* Wf2    = (const float*)d_in[15];
    const float* Wl1    = (const float*)d_in[16];
    const float* Wl2    = (const float*)d_in[17];
    const float* Wo_s   = (const float*)d_in[18];
    const float* bo_s   = (const float*)d_in[19];
    const float* Wo_v   = (const float*)d_in[20];

    int N = in_sizes[0] / 320;
    int E = in_sizes[1] / 2;
    float* out = (float*)d_out;

    float *p_xvT, *p_f0, *p_pre_s, *p_pre_v, *p_h1, *p_g, *p_xv2T, *p_xs3, *p_ns, *p_nv, *p_xv3;
    cudaGetSymbolAddress((void**)&p_xvT,  g_xvT);
    cudaGetSymbolAddress((void**)&p_f0,   g_f0);
    cudaGetSymbolAddress((void**)&p_pre_s,g_pre_s);
    cudaGetSymbolAddress((void**)&p_pre_v,g_pre_v);
    cudaGetSymbolAddress((void**)&p_h1,   g_h1);
    cudaGetSymbolAddress((void**)&p_g,    g_g);
    cudaGetSymbolAddress((void**)&p_xv2T, g_xv2T);
    cudaGetSymbolAddress((void**)&p_xs3,  g_xs3);
    cudaGetSymbolAddress((void**)&p_ns,   g_ns);
    cudaGetSymbolAddress((void**)&p_nv,   g_nv);
    cudaGetSymbolAddress((void**)&p_xv3,  g_xv3);

    const float s128 = 0.08838834764831845f;
    const float s64  = 0.125f;
    const float s192 = 0.07216878364870323f;

    detect_kernel<<<1, 32>>>(ei_raw);
    convert_kernel<<<512, 256>>>(ei_raw, 2 * E);

    // dst counting sort
    zcnt_kernel<<<64, 256>>>(N);
    hist_kernel<<<512, 256>>>(E);
    scan_kernel<<<1, 1024>>>(N);
    scatter_kernel<<<512, 256>>>(E);

    prep_kernel<<<2048, 256>>>(x, N);

    // Phase A: pre_s | pre_v | h1
    {
        GemmJob jA = mkjob(x, 320, Wpre_s, 128, p_pre_s, 128, N, 128, 128, s128, bpre_s, 0, 0, 0, 0);
        int c0 = jA.gx * jA.gy;
        GemmJob jB = mkjob(p_xvT, 64, Wpre_v, 64, p_pre_v, 64, 3 * N, 64, 64, s64, nullptr, 0, 0, 0, c0);
        int c1 = c0 + jB.gx * jB.gy;
        GemmJob jC = mkjob(p_f0, 192, Wg1, 192, p_h1, 192, N, 192, 192, 1.f, bg1, 1, 0, 0, c1);
        int total = c1 + jC.gx * jC.gy;
        gemm_multi<<<total, 256>>>(jA, jB, jC);
    }
    // g = h1 @ Wg2 + bg2
    {
        GemmJob jA = mkjob(p_h1, 192, Wg2, 192, p_g, 192, N, 192, 192, 1.f, bg2, 0, 0, 0, 0);
        int total = jA.gx * jA.gy;
        GemmJob jX = jA; jX.off = total;
        gemm_multi<<<total, 256>>>(jA, jX, jX);
    }

    gate_kernel<<<2048, 256>>>(N);
    wsum_kernel<<<16, 256>>>(Wl1);
    nl1_kernel<<<(N + 7) / 8, 256>>>(N);

    // Phase B: xs3 (K=128) | xv3
    {
        GemmJob jA = mkjob(p_g, 192, Wn_s, 128, p_xs3, 128, N, 128, 128, s128, bn_s, 0, 0, 0, 0);
        int c0 = jA.gx * jA.gy;
        GemmJob jB = mkjob(p_xv2T, 64, Wn_v, 64, p_xv3, 64, 3 * N, 64, 64, s64, nullptr, 0, 0, 0, c0);
        int total = c0 + jB.gx * jB.gy;
        GemmJob jX = jB; jX.off = total;
        gemm_multi<<<total, 256>>>(jA, jB, jX);
    }

    zero_kernel<<<2048, 256>>>(N);

    cudaFuncSetAttribute(edge_kernel, cudaFuncAttributeMaxDynamicSharedMemorySize,
                         EDGE_SMEM_BYTES);
    edge_kernel<<<148, ETHREADS, EDGE_SMEM_BYTES>>>(ea, esh, Wf1, Wf2, Wl1, Wl2, E, N);

    // Phase C: outs | outv
    {
        GemmJob jA = mkjob(p_ns, 192, Wo_s, 256, out, 640, N, 192, 256, s192, bo_s, 0, 0, 0, 0);
        int c0 = jA.gx * jA.gy;
        GemmJob jB = mkjob(p_nv, 192, Wo_v, 128, out, 0, 3 * N, 192, 128, s192, nullptr, 0, 1, N, c0);
        int total = c0 + jB.gx * jB.gy;
        GemmJob jX = jB; jX.off = total;
        gemm_multi<<<total, 256>>>(jA, jB, jX);
    }
}

// round 14
// speedup vs baseline: 1.3413x; 1.0688x over previous
#include <cuda_runtime.h>
#include <math.h>

#define NMAX 16000
#define EMAX 256000

// ---------------- static device scratch ----------------
__device__ float g_xvT [3*NMAX*64];
__device__ float g_f0  [NMAX*192];
__device__ float g_pre_s[NMAX*128];
__device__ float g_pre_v[3*NMAX*64];
__device__ float g_h1  [NMAX*192];
__device__ float g_g   [NMAX*192];
__device__ float g_xv2T[3*NMAX*64];
__device__ float g_xs3 [NMAX*128];
__device__ float g_xv3 [3*NMAX*64];
__device__ float g_ns  [NMAX*192];
__device__ float g_nv  [3*NMAX*192];
__device__ float g_nl1 [NMAX*32];
__device__ float g_Wl1c[128*32];
__device__ int   g_ei  [2*EMAX];

// ---------------- edge-index convert with inline dtype detection ----------------
// int64 values < 2^31: every odd 32-bit word is 0; int32 data: odd words are
// random node indices (P[all 128 zero] ~ 0). Each block detects from L2-hot words.
__global__ void convert_kernel(const int* __restrict__ ei_raw, int total) {
    __shared__ int s_is64;
    if (threadIdx.x == 0) {
        int nz = 0;
        for (int i = 1; i < 256; i += 2) nz += (ei_raw[i] != 0);
        s_is64 = (nz == 0) ? 1 : 0;
    }
    __syncthreads();
    int is64 = s_is64;
    for (int idx = blockIdx.x * blockDim.x + threadIdx.x; idx < total;
         idx += gridDim.x * blockDim.x)
        g_ei[idx] = is64 ? ei_raw[2 * idx] : ei_raw[idx];
}

// ---------------- prep ----------------
__global__ void prep_kernel(const float* __restrict__ x, int N) {
    int total = N * 192;
    for (int idx = blockIdx.x * blockDim.x + threadIdx.x; idx < total;
         idx += gridDim.x * blockDim.x) {
        int n = idx / 192, i = idx - n * 192;
        if (i < 128) {
            g_f0[n * 192 + i] = x[n * 320 + i];
        } else {
            int u = i - 128;
            float a = x[n * 320 + 128 + 3 * u + 0];
            float b = x[n * 320 + 128 + 3 * u + 1];
            float c = x[n * 320 + 128 + 3 * u + 2];
            g_xvT[(0 * N + n) * 64 + u] = a;
            g_xvT[(1 * N + n) * 64 + u] = b;
            g_xvT[(2 * N + n) * 64 + u] = c;
            g_f0[n * 192 + i] = sqrtf(a * a + b * b + c * c + 1e-12f);
        }
    }
}

__global__ void gate_kernel(int N) {
    int total = 3 * N * 64;
    for (int idx = blockIdx.x * blockDim.x + threadIdx.x; idx < total;
         idx += gridDim.x * blockDim.x) {
        int rem = idx % (N * 64);
        int n = rem / 64, u = rem - n * 64;
        g_xv2T[idx] = g_xvT[idx] * g_g[n * 192 + 128 + u];
    }
}

__global__ void zero_kernel(int N) {
    int t1 = N * 192, t2 = 3 * N * 192, total = t1 + t2;
    for (int idx = blockIdx.x * blockDim.x + threadIdx.x; idx < total;
         idx += gridDim.x * blockDim.x) {
        if (idx < t1) g_ns[idx] = 0.f;
        else          g_nv[idx - t1] = 0.f;
    }
}

__global__ void wsum_kernel(const float* __restrict__ Wl1) {
    int idx = blockIdx.x * blockDim.x + threadIdx.x;
    if (idx < 128 * 32) g_Wl1c[idx] = Wl1[idx] + Wl1[128 * 32 + idx];
}

__global__ void nl1_kernel(int N) {
    __shared__ float sW[128 * 32];
    int tid = threadIdx.x;
    for (int i = tid; i < 128 * 32; i += 256) sW[i] = g_Wl1c[i];
    __syncthreads();
    int j = tid & 31;
    int n = blockIdx.x * 8 + (tid >> 5);
    if (n >= N) return;
    const float* row = &g_pre_s[(size_t)n * 128];
    float acc = 0.f;
#pragma unroll 8
    for (int q = 0; q < 128; q++) acc += row[q] * sW[q * 32 + j];
    g_nl1[(size_t)n * 32 + j] = acc;
}

// ---------------- multi-job SGEMM, flat 1D grid (round-9 proven) ----------------
struct GemmJob {
    const float* X; const float* W; float* C; const float* bias;
    int ldx, ldw, ldc;
    int K;
    float scale;
    int act, out_mode, nnodes;
    int gx, gy, off;
};

__device__ __forceinline__ void gemm_body(const GemmJob& jb, int bx, int by) {
    __shared__ __align__(16) float sX[2][16][132];
    __shared__ __align__(16) float sW[2][16][68];
    int bm = by * 128, bo = bx * 64;
    int tid = threadIdx.x;
    int tr = tid >> 4, tc = tid & 15;
    int m0 = tr * 8, o0 = tc * 4;

    float acc[8][4];
#pragma unroll
    for (int i = 0; i < 8; i++)
#pragma unroll
        for (int j = 0; j < 4; j++) acc[i][j] = 0.f;

    int xr[8], xc[8];
#pragma unroll
    for (int l = 0; l < 8; l++) {
        int i = tid + l * 256;
        xr[l] = i >> 4; xc[l] = i & 15;
    }
    int wr[4], wc[4];
#pragma unroll
    for (int l = 0; l < 4; l++) {
        int i = tid + l * 256;
        wr[l] = i >> 6; wc[l] = i & 63;
    }

    int ntiles = jb.K >> 4;
    float rx[8], rw[4];
#pragma unroll
    for (int l = 0; l < 8; l++)
        rx[l] = jb.X[(long long)(bm + xr[l]) * jb.ldx + xc[l]];
#pragma unroll
    for (int l = 0; l < 4; l++)
        rw[l] = jb.W[(long long)wr[l] * jb.ldw + bo + wc[l]];

    for (int t = 0; t < ntiles; t++) {
        int buf = t & 1;
#pragma unroll
        for (int l = 0; l < 8; l++) sX[buf][xc[l]][xr[l]] = rx[l];
#pragma unroll
        for (int l = 0; l < 4; l++) sW[buf][wr[l]][wc[l]] = rw[l];
        __syncthreads();
        if (t + 1 < ntiles) {
            int k0 = (t + 1) << 4;
#pragma unroll
            for (int l = 0; l < 8; l++)
                rx[l] = jb.X[(long long)(bm + xr[l]) * jb.ldx + k0 + xc[l]];
#pragma unroll
            for (int l = 0; l < 4; l++)
                rw[l] = jb.W[(long long)(k0 + wr[l]) * jb.ldw + bo + wc[l]];
        }
#pragma unroll
        for (int k = 0; k < 16; k++) {
            float4 a0 = *reinterpret_cast<const float4*>(&sX[buf][k][m0]);
            float4 a1 = *reinterpret_cast<const float4*>(&sX[buf][k][m0 + 4]);
            float4 b  = *reinterpret_cast<const float4*>(&sW[buf][k][o0]);
            float av[8] = {a0.x, a0.y, a0.z, a0.w, a1.x, a1.y, a1.z, a1.w};
            float bv[4] = {b.x, b.y, b.z, b.w};
#pragma unroll
            for (int i = 0; i < 8; i++)
#pragma unroll
                for (int j = 0; j < 4; j++) acc[i][j] += av[i] * bv[j];
        }
        __syncthreads();
    }

#pragma unroll
    for (int i = 0; i < 8; i++) {
        int m = bm + m0 + i;
#pragma unroll
        for (int j = 0; j < 4; j++) {
            int o = bo + o0 + j;
            float v = acc[i][j] * jb.scale;
            if (jb.bias) v += jb.bias[o];
            if (jb.act == 1) v = v / (1.f + expf(-v));
            if (jb.out_mode == 0) {
                jb.C[(long long)m * jb.ldc + o] = v;
            } else {
                int cc = m / jb.nnodes;
                int n = m - cc * jb.nnodes;
                jb.C[(long long)n * 640 + 256 + o * 3 + cc] = v;
            }
        }
    }
}

__global__ void __launch_bounds__(256)
gemm_multi(GemmJob j0, GemmJob j1, GemmJob j2) {
    int b = blockIdx.x;
    GemmJob jb = (b >= j2.off) ? j2 : (b >= j1.off) ? j1 : j0;
    int local = b - jb.off;
    gemm_body(jb, local % jb.gx, local / jb.gx);
}

// ---------------- helpers ----------------
__device__ __forceinline__ void red4(float* addr, float a, float b, float c, float d) {
    asm volatile("red.global.add.v4.f32 [%0], {%1,%2,%3,%4};"
                 :: "l"(addr), "f"(a), "f"(b), "f"(c), "f"(d) : "memory");
}
__device__ __forceinline__ float ssp_f(float x) {
    const float ln2 = 0.69314718055994531f;
    return fmaxf(x, 0.f) + log1pf(expf(-fabsf(x))) - ln2;
}

// ---------------- fused edge kernel (round-9 champion, inv32 folded) ----------------
#define ETILE 96
#define ETHREADS 768
#define OFF_WF1 0
#define OFF_WF2 (OFF_WF1 + 1024)
#define OFF_WC  (OFF_WF2 + 12288)
#define OFF_WL2 (OFF_WC + 2048)
#define OFF_EA  (OFF_WL2 + 12288)
#define OFF_NL  (OFF_EA + 96*33)
#define OFF_IP  (OFF_NL + 96*33)
#define OFF_EAT (OFF_IP + 96*65)
#define OFF_IPT (OFF_EAT + 32*96)
#define OFF_HF  (OFF_IPT + 64*96)
#define OFF_HL  (OFF_HF + 32*96)
#define OFF_SH  (OFF_HL + 32*96)
#define OFF_END (OFF_SH + 384)
#define EDGE_SMEM_BYTES (OFF_END*4 + 192*4)

__global__ void __launch_bounds__(ETHREADS, 1)
edge_kernel(const float* __restrict__ edge_attr,
            const float* __restrict__ edge_sh,
            const float* __restrict__ Wf1, const float* __restrict__ Wf2,
            const float* __restrict__ Wl1, const float* __restrict__ Wl2,
            int E, int N) {
    extern __shared__ float sm[];
    float* sWf1 = sm + OFF_WF1;
    float* sWf2 = sm + OFF_WF2;
    float* sWc  = sm + OFF_WC;
    float* sWl2 = sm + OFF_WL2;
    float* sea  = sm + OFF_EA;
    float* snl  = sm + OFF_NL;
    float* sip  = sm + OFF_IP;
    float* seaT = sm + OFF_EAT;
    float* sipT = sm + OFF_IPT;
    float* shfT = sm + OFF_HF;
    float* shlT = sm + OFF_HL;
    float* ssh  = sm + OFF_SH;
    int*   sidx = (int*)(sm + OFF_END);

    int tid = threadIdx.x;
    for (int i = tid; i < 1024;  i += ETHREADS) sWf1[i] = Wf1[i];
    for (int i = tid; i < 12288; i += ETHREADS) sWf2[i] = Wf2[i];
    for (int i = tid; i < 2048;  i += ETHREADS) sWc[i]  = Wl1[256 * 32 + i];
    for (int i = tid; i < 12288; i += ETHREADS) sWl2[i] = Wl2[i];

    const float c0 = 0.5f, c1 = 0.86602540378443865f;
    const float inv3 = 1.f / 3.f;
    const float invs32 = 0.17677669529663687f;     // 1/sqrt(32)
    const float invs320 = 0.05590169943749474f;
    const float invs3 = 0.57735026918962576f;
    // fold 1/32 = invs32^2 into hf and hl activations (w = (hf.af)(hl.al)/32)

    int warp = tid >> 5, lane = tid & 31;
    int eb = warp * 4;

    int ntiles = (E + ETILE - 1) / ETILE;
    for (int tile = blockIdx.x; tile < ntiles; tile += gridDim.x) {
        int e0 = tile * ETILE;
        int cnt = min(ETILE, E - e0);
        __syncthreads();

        if (tid < ETILE) {
            int valid = tid < cnt;
            sidx[tid]         = valid ? g_ei[e0 + tid]     : 0;
            sidx[ETILE + tid] = valid ? g_ei[E + e0 + tid] : 0;
        }
        for (int i = tid; i < ETILE * 4; i += ETHREADS) {
            int t = i >> 2, q = i & 3;
            ssh[i] = (t < cnt) ? edge_sh[(size_t)(e0 + t) * 4 + q] : 0.f;
        }
        for (int i = tid; i < ETILE * 32; i += ETHREADS) {
            int t = i >> 5, q = i & 31;
            sea[t * 33 + q] = (t < cnt) ? edge_attr[(size_t)(e0 + t) * 32 + q] : 0.f;
        }
        __syncthreads();

        for (int i = tid; i < ETILE * 64; i += ETHREADS) {
            int t = i >> 6, u = i & 63;
            int d = sidx[t], s = sidx[ETILE + t];
            float acc = 0.f;
#pragma unroll
            for (int c = 0; c < 3; c++)
                acc += g_pre_v[((size_t)c * N + d) * 64 + u] *
                       g_pre_v[((size_t)c * N + s) * 64 + u];
            sip[t * 65 + u] = acc * inv3;
        }
        for (int i = tid; i < ETILE * 32; i += ETHREADS) {
            int t = i >> 5, j = i & 31;
            snl[t * 33 + j] = g_nl1[(size_t)sidx[t] * 32 + j];
        }
        __syncthreads();

        for (int i = tid; i < 32 * ETILE; i += ETHREADS) {
            int t = i % ETILE, q = i / ETILE;
            seaT[q * ETILE + t] = sea[t * 33 + q];
        }
        for (int i = tid; i < 64 * ETILE; i += ETHREADS) {
            int t = i % ETILE, u = i / ETILE;
            sipT[u * ETILE + t] = sip[t * 65 + u];
        }
        __syncthreads();

        // MLP-1 register-blocked, warp-split; inv32 folded into outputs
        if (warp < 6) {
            int idx = tid;
            int t0 = (idx % 24) * 4, j0 = (idx / 24) * 4;
            float acc[4][4];
#pragma unroll
            for (int a = 0; a < 4; a++)
#pragma unroll
                for (int b = 0; b < 4; b++) acc[a][b] = 0.f;
#pragma unroll 4
            for (int q = 0; q < 32; q++) {
                float4 hv = *reinterpret_cast<const float4*>(&seaT[q * ETILE + t0]);
                float4 wv = *reinterpret_cast<const float4*>(&sWf1[q * 32 + j0]);
                float h[4] = {hv.x, hv.y, hv.z, hv.w};
                float w[4] = {wv.x, wv.y, wv.z, wv.w};
#pragma unroll
                for (int a = 0; a < 4; a++)
#pragma unroll
                    for (int b = 0; b < 4; b++) acc[a][b] += h[a] * w[b];
            }
#pragma unroll
            for (int b = 0; b < 4; b++) {
                float4 o;
                o.x = ssp_f(acc[0][b] * invs32) * invs32;
                o.y = ssp_f(acc[1][b] * invs32) * invs32;
                o.z = ssp_f(acc[2][b] * invs32) * invs32;
                o.w = ssp_f(acc[3][b] * invs32) * invs32;
                *reinterpret_cast<float4*>(&shfT[(j0 + b) * ETILE + t0]) = o;
            }
        } else if (warp < 18) {
            int idx = tid - 192;
            int t0 = (idx % 48) * 2, j0 = (idx / 48) * 4;
            float acc[2][4];
#pragma unroll
            for (int a = 0; a < 2; a++)
#pragma unroll
                for (int b = 0; b < 4; b++) acc[a][b] = snl[(t0 + a) * 33 + j0 + b];
#pragma unroll 4
            for (int u = 0; u < 64; u++) {
                float2 hv = *reinterpret_cast<const float2*>(&sipT[u * ETILE + t0]);
                float4 wv = *reinterpret_cast<const float4*>(&sWc[u * 32 + j0]);
                float h[2] = {hv.x, hv.y};
                float w[4] = {wv.x, wv.y, wv.z, wv.w};
#pragma unroll
                for (int a = 0; a < 2; a++)
#pragma unroll
                    for (int b = 0; b < 4; b++) acc[a][b] += h[a] * w[b];
            }
#pragma unroll
            for (int b = 0; b < 4; b++) {
                float2 o;
                o.x = ssp_f(acc[0][b] * invs320) * invs32;
                o.y = ssp_f(acc[1][b] * invs320) * invs32;
                *reinterpret_cast<float2*>(&shlT[(j0 + b) * ETILE + t0]) = o;
            }
        }
        __syncthreads();

        // layer 2: per thread 4 edges x 4 outputs, 3 output blocks
#pragma unroll 1
        for (int ob = 0; ob < 3; ob++) {
            int o0 = ob * 128 + lane * 4;
            float wf[4][4], wl[4][4];
#pragma unroll
            for (int a = 0; a < 4; a++)
#pragma unroll
                for (int b = 0; b < 4; b++) { wf[a][b] = 0.f; wl[a][b] = 0.f; }

#pragma unroll 2
            for (int j = 0; j < 32; j++) {
                float4 hf = *reinterpret_cast<const float4*>(&shfT[j * ETILE + eb]);
                float4 hl = *reinterpret_cast<const float4*>(&shlT[j * ETILE + eb]);
                float4 af = *reinterpret_cast<const float4*>(&sWf2[j * 384 + o0]);
                float4 al = *reinterpret_cast<const float4*>(&sWl2[j * 384 + o0]);
                float hfv[4] = {hf.x, hf.y, hf.z, hf.w};
                float hlv[4] = {hl.x, hl.y, hl.z, hl.w};
                float afv[4] = {af.x, af.y, af.z, af.w};
                float alv[4] = {al.x, al.y, al.z, al.w};
#pragma unroll
                for (int a = 0; a < 4; a++)
#pragma unroll
                    for (int b = 0; b < 4; b++) {
                        wf[a][b] += hfv[a] * afv[b];
                        wl[a][b] += hlv[a] * alv[b];
                    }
            }

#pragma unroll
            for (int a = 0; a < 4; a++) {
                int t = eb + a;
                if (t >= cnt) continue;
                int d = sidx[t], s = sidx[ETILE + t];
                float sh0 = ssh[t * 4 + 0];
                float w0 = wf[a][0] * wl[a][0];
                float w1 = wf[a][1] * wl[a][1];
                float w2 = wf[a][2] * wl[a][2];
                float w3 = wf[a][3] * wl[a][3];
                if (o0 < 128) {
                    float4 hs = *reinterpret_cast<const float4*>(&g_xs3[(size_t)s * 128 + o0]);
                    float k = c0 * sh0;
                    red4(&g_ns[(size_t)d * 192 + o0],
                         k * w0 * hs.x, k * w1 * hs.y, k * w2 * hs.z, k * w3 * hs.w);
                } else if (o0 < 256) {
                    int u0 = o0 - 128;
                    float4 hs = *reinterpret_cast<const float4*>(&g_xs3[(size_t)s * 128 + u0]);
                    float b0 = c1 * w0 * hs.x, b1 = c1 * w1 * hs.y;
                    float b2 = c1 * w2 * hs.z, b3 = c1 * w3 * hs.w;
#pragma unroll
                    for (int c = 0; c < 3; c++) {
                        float shc = ssh[t * 4 + 1 + c];
                        red4(&g_nv[((size_t)c * N + d) * 192 + u0],
                             b0 * shc, b1 * shc, b2 * shc, b3 * shc);
                    }
                } else if (o0 < 320) {
                    int u0 = o0 - 256;
                    float b0 = c1 * w0 * sh0, b1 = c1 * w1 * sh0;
                    float b2 = c1 * w2 * sh0, b3 = c1 * w3 * sh0;
#pragma unroll
                    for (int c = 0; c < 3; c++) {
                        float4 hv = *reinterpret_cast<const float4*>(
                            &g_xv3[((size_t)c * N + s) * 64 + u0]);
                        red4(&g_nv[((size_t)c * N + d) * 192 + 128 + u0],
                             b0 * hv.x, b1 * hv.y, b2 * hv.z, b3 * hv.w);
                    }
                } else {
                    int u0 = o0 - 320;
                    float4 hx = *reinterpret_cast<const float4*>(&g_xv3[((size_t)0 * N + s) * 64 + u0]);
                    float4 hy = *reinterpret_cast<const float4*>(&g_xv3[((size_t)1 * N + s) * 64 + u0]);
                    float4 hz = *reinterpret_cast<const float4*>(&g_xv3[((size_t)2 * N + s) * 64 + u0]);
                    float sh1 = ssh[t * 4 + 1], sh2v = ssh[t * 4 + 2], sh3 = ssh[t * 4 + 3];
                    float k = c0 * invs3;
                    red4(&g_ns[(size_t)d * 192 + 128 + u0],
                         k * w0 * (hx.x * sh1 + hy.x * sh2v + hz.x * sh3),
                         k * w1 * (hx.y * sh1 + hy.y * sh2v + hz.y * sh3),
                         k * w2 * (hx.z * sh1 + hy.z * sh2v + hz.z * sh3),
                         k * w3 * (hx.w * sh1 + hy.w * sh2v + hz.w * sh3));
                }
            }
        }
    }
}

// ---------------- launch ----------------
static GemmJob mkjob(const float* X, int ldx, const float* W, int ldw,
                     float* C, int ldc, int M, int K, int O,
                     float scale, const float* bias, int act,
                     int out_mode, int nnodes, int off) {
    GemmJob j;
    j.X = X; j.W = W; j.C = C; j.bias = bias;
    j.ldx = ldx; j.ldw = ldw; j.ldc = ldc;
    j.K = K; j.scale = scale; j.act = act;
    j.out_mode = out_mode; j.nnodes = nnodes;
    j.gx = O / 64; j.gy = M / 128; j.off = off;
    return j;
}

extern "C" void kernel_launch(void* const* d_in, const int* in_sizes, int n_in,
                              void* d_out, int out_size) {
    const float* x      = (const float*)d_in[0];
    const int*   ei_raw = (const int*)d_in[1];
    const float* ea     = (const float*)d_in[2];
    const float* esh    = (const float*)d_in[3];
    const float* Wpre_s = (const float*)d_in[4];
    const float* bpre_s = (const float*)d_in[5];
    const float* Wpre_v = (const float*)d_in[6];
    const float* Wg1    = (const float*)d_in[7];
    const float* bg1    = (const float*)d_in[8];
    const float* Wg2    = (const float*)d_in[9];
    const float* bg2    = (const float*)d_in[10];
    const float* Wn_s   = (const float*)d_in[11];
    const float* bn_s   = (const float*)d_in[12];
    const float* Wn_v   = (const float*)d_in[13];
    const float* Wf1    = (const float*)d_in[14];
    const float* Wf2    = (const float*)d_in[15];
    const float* Wl1    = (const float*)d_in[16];
    const float* Wl2    = (const float*)d_in[17];
    const float* Wo_s   = (const float*)d_in[18];
    const float* bo_s   = (const float*)d_in[19];
    const float* Wo_v   = (const float*)d_in[20];

    int N = in_sizes[0] / 320;
    int E = in_sizes[1] / 2;
    float* out = (float*)d_out;

    float *p_xvT, *p_f0, *p_pre_s, *p_pre_v, *p_h1, *p_g, *p_xv2T, *p_xs3, *p_ns, *p_nv, *p_xv3;
    cudaGetSymbolAddress((void**)&p_xvT,  g_xvT);
    cudaGetSymbolAddress((void**)&p_f0,   g_f0);
    cudaGetSymbolAddress((void**)&p_pre_s,g_pre_s);
    cudaGetSymbolAddress((void**)&p_pre_v,g_pre_v);
    cudaGetSymbolAddress((void**)&p_h1,   g_h1);
    cudaGetSymbolAddress((void**)&p_g,    g_g);
    cudaGetSymbolAddress((void**)&p_xv2T, g_xv2T);
    cudaGetSymbolAddress((void**)&p_xs3,  g_xs3);
    cudaGetSymbolAddress((void**)&p_ns,   g_ns);
    cudaGetSymbolAddress((void**)&p_nv,   g_nv);
    cudaGetSymbolAddress((void**)&p_xv3,  g_xv3);

    const float s128 = 0.08838834764831845f;
    const float s64  = 0.125f;
    const float s192 = 0.07216878364870323f;

    convert_kernel<<<512, 256>>>(ei_raw, 2 * E);
    prep_kernel<<<2048, 256>>>(x, N);

    // Phase A: pre_s | pre_v | h1
    {
        GemmJob jA = mkjob(x, 320, Wpre_s, 128, p_pre_s, 128, N, 128, 128, s128, bpre_s, 0, 0, 0, 0);
        int c0 = jA.gx * jA.gy;
        GemmJob jB = mkjob(p_xvT, 64, Wpre_v, 64, p_pre_v, 64, 3 * N, 64, 64, s64, nullptr, 0, 0, 0, c0);
        int c1 = c0 + jB.gx * jB.gy;
        GemmJob jC = mkjob(p_f0, 192, Wg1, 192, p_h1, 192, N, 192, 192, 1.f, bg1, 1, 0, 0, c1);
        int total = c1 + jC.gx * jC.gy;
        gemm_multi<<<total, 256>>>(jA, jB, jC);
    }
    // g = h1 @ Wg2 + bg2
    {
        GemmJob jA = mkjob(p_h1, 192, Wg2, 192, p_g, 192, N, 192, 192, 1.f, bg2, 0, 0, 0, 0);
        int total = jA.gx * jA.gy;
        GemmJob jX = jA; jX.off = total;
        gemm_multi<<<total, 256>>>(jA, jX, jX);
    }

    gate_kernel<<<2048, 256>>>(N);
    wsum_kernel<<<16, 256>>>(Wl1);
    nl1_kernel<<<(N + 7) / 8, 256>>>(N);

    // Phase B: xs3 (K=128) | xv3
    {
        GemmJob jA = mkjob(p_g, 192, Wn_s, 128, p_xs3, 128, N, 128, 128, s128, bn_s, 0, 0, 0, 0);
        int c0 = jA.gx * jA.gy;
        GemmJob jB = mkjob(p_xv2T, 64, Wn_v, 64, p_xv3, 64, 3 * N, 64, 64, s64, nullptr, 0, 0, 0, c0);
        int total = c0 + jB.gx * jB.gy;
        GemmJob jX = jB; jX.off = total;
        gemm_multi<<<total, 256>>>(jA, jB, jX);
    }

    zero_kernel<<<2048, 256>>>(N);

    cudaFuncSetAttribute(edge_kernel, cudaFuncAttributeMaxDynamicSharedMemorySize,
                         EDGE_SMEM_BYTES);
    edge_kernel<<<148, ETHREADS, EDGE_SMEM_BYTES>>>(ea, esh, Wf1, Wf2, Wl1, Wl2, E, N);

    // Phase C: outs | outv
    {
        GemmJob jA = mkjob(p_ns, 192, Wo_s, 256, out, 640, N, 192, 256, s192, bo_s, 0, 0, 0, 0);
        int c0 = jA.gx * jA.gy;
        GemmJob jB = mkjob(p_nv, 192, Wo_v, 128, out, 0, 3 * N, 192, 128, s192, nullptr, 0, 1, N, c0);
        int total = c0 + jB.gx * jB.gy;
        GemmJob jX = jB; jX.off = total;
        gemm_multi<<<total, 256>>>(jA, jB, jX);
    }
}

// round 15
// speedup vs baseline: 1.4155x; 1.0553x over previous
#include <cuda_runtime.h>
#include <math.h>

#define NMAX 16000
#define EMAX 256000

// ---------------- static device scratch ----------------
__device__ float g_xvT [3*NMAX*64];
__device__ float g_f0  [NMAX*192];
__device__ float g_pre_s[NMAX*128];
__device__ float g_pre_v[3*NMAX*64];
__device__ float g_h1  [NMAX*192];
__device__ float g_g   [NMAX*192];
__device__ float g_xv2T[3*NMAX*64];
__device__ float g_xs3 [NMAX*128];
__device__ float g_xv3 [3*NMAX*64];
__device__ float g_ns  [NMAX*192];
__device__ float g_nv  [3*NMAX*192];
__device__ float g_nl1 [NMAX*32];
__device__ float g_Wl1c[128*32];
__device__ int   g_ei  [2*EMAX];

// ---------------- edge-index convert with inline dtype detection ----------------
__global__ void convert_kernel(const int* __restrict__ ei_raw, int total) {
    __shared__ int s_is64;
    if (threadIdx.x == 0) {
        int nz = 0;
        for (int i = 1; i < 256; i += 2) nz += (ei_raw[i] != 0);
        s_is64 = (nz == 0) ? 1 : 0;
    }
    __syncthreads();
    int is64 = s_is64;
    for (int idx = blockIdx.x * blockDim.x + threadIdx.x; idx < total;
         idx += gridDim.x * blockDim.x)
        g_ei[idx] = is64 ? ei_raw[2 * idx] : ei_raw[idx];
}

// ---------------- prep ----------------
__global__ void prep_kernel(const float* __restrict__ x, int N) {
    int total = N * 192;
    for (int idx = blockIdx.x * blockDim.x + threadIdx.x; idx < total;
         idx += gridDim.x * blockDim.x) {
        int n = idx / 192, i = idx - n * 192;
        if (i < 128) {
            g_f0[n * 192 + i] = x[n * 320 + i];
        } else {
            int u = i - 128;
            float a = x[n * 320 + 128 + 3 * u + 0];
            float b = x[n * 320 + 128 + 3 * u + 1];
            float c = x[n * 320 + 128 + 3 * u + 2];
            g_xvT[(0 * N + n) * 64 + u] = a;
            g_xvT[(1 * N + n) * 64 + u] = b;
            g_xvT[(2 * N + n) * 64 + u] = c;
            g_f0[n * 192 + i] = sqrtf(a * a + b * b + c * c + 1e-12f);
        }
    }
}

__global__ void gate_kernel(int N) {
    int total = 3 * N * 64;
    for (int idx = blockIdx.x * blockDim.x + threadIdx.x; idx < total;
         idx += gridDim.x * blockDim.x) {
        int rem = idx % (N * 64);
        int n = rem / 64, u = rem - n * 64;
        g_xv2T[idx] = g_xvT[idx] * g_g[n * 192 + 128 + u];
    }
}

__global__ void zero_kernel(int N) {
    int t1 = N * 192, t2 = 3 * N * 192, total = t1 + t2;
    for (int idx = blockIdx.x * blockDim.x + threadIdx.x; idx < total;
         idx += gridDim.x * blockDim.x) {
        if (idx < t1) g_ns[idx] = 0.f;
        else          g_nv[idx - t1] = 0.f;
    }
}

__global__ void wsum_kernel(const float* __restrict__ Wl1) {
    int idx = blockIdx.x * blockDim.x + threadIdx.x;
    if (idx < 128 * 32) g_Wl1c[idx] = Wl1[idx] + Wl1[128 * 32 + idx];
}

__global__ void nl1_kernel(int N) {
    __shared__ float sW[128 * 32];
    int tid = threadIdx.x;
    for (int i = tid; i < 128 * 32; i += 256) sW[i] = g_Wl1c[i];
    __syncthreads();
    int j = tid & 31;
    int n = blockIdx.x * 8 + (tid >> 5);
    if (n >= N) return;
    const float* row = &g_pre_s[(size_t)n * 128];
    float acc = 0.f;
#pragma unroll 8
    for (int q = 0; q < 128; q++) acc += row[q] * sW[q * 32 + j];
    g_nl1[(size_t)n * 32 + j] = acc;
}

// ---------------- cp.async helpers ----------------
__device__ __forceinline__ void cp_async4(unsigned saddr, const float* gptr) {
    asm volatile("cp.async.ca.shared.global [%0], [%1], 4;" :: "r"(saddr), "l"(gptr));
}
__device__ __forceinline__ void cp_commit() {
    asm volatile("cp.async.commit_group;" ::: "memory");
}
__device__ __forceinline__ void cp_wait1() {
    asm volatile("cp.async.wait_group 1;" ::: "memory");
}
__device__ __forceinline__ void cp_wait0() {
    asm volatile("cp.async.wait_group 0;" ::: "memory");
}

// ---------------- multi-job SGEMM, flat 1D grid, cp.async double-buffered ----------------
struct GemmJob {
    const float* X; const float* W; float* C; const float* bias;
    int ldx, ldw, ldc;
    int K;
    float scale;
    int act, out_mode, nnodes;
    int gx, gy, off;
};

__device__ __forceinline__ void gemm_body(const GemmJob& jb, int bx, int by) {
    __shared__ __align__(16) float sX[2][16][132];
    __shared__ __align__(16) float sW[2][16][68];
    int bm = by * 128, bo = bx * 64;
    int tid = threadIdx.x;
    int tr = tid >> 4, tc = tid & 15;
    int m0 = tr * 8, o0 = tc * 4;

    float acc[8][4];
#pragma unroll
    for (int i = 0; i < 8; i++)
#pragma unroll
        for (int j = 0; j < 4; j++) acc[i][j] = 0.f;

    // per-thread copy slots: smem byte addresses (buf0) + gmem int offsets
    unsigned sxa[8], swa[4];
    int gxo[8], gwo[4];
#pragma unroll
    for (int l = 0; l < 8; l++) {
        int i = tid + l * 256;
        int r = i >> 4, c = i & 15;
        sxa[l] = (unsigned)__cvta_generic_to_shared(&sX[0][c][r]);
        gxo[l] = (bm + r) * jb.ldx + c;
    }
#pragma unroll
    for (int l = 0; l < 4; l++) {
        int i = tid + l * 256;
        int r = i >> 6, c = i & 63;
        swa[l] = (unsigned)__cvta_generic_to_shared(&sW[0][r][c]);
        gwo[l] = r * jb.ldw + bo + c;
    }
    const unsigned SXB = 16 * 132 * 4;
    const unsigned SWB = 16 * 68 * 4;

    int ntiles = jb.K >> 4;
    // prologue: tile 0 -> buf 0
#pragma unroll
    for (int l = 0; l < 8; l++) cp_async4(sxa[l], jb.X + gxo[l]);
#pragma unroll
    for (int l = 0; l < 4; l++) cp_async4(swa[l], jb.W + gwo[l]);
    cp_commit();

    for (int t = 0; t < ntiles; t++) {
        if (t + 1 < ntiles) {
            int k0 = (t + 1) << 4;
            unsigned bofX = ((t + 1) & 1) ? SXB : 0u;
            unsigned bofW = ((t + 1) & 1) ? SWB : 0u;
            int wstep = k0 * jb.ldw;
#pragma unroll
            for (int l = 0; l < 8; l++)
                cp_async4(sxa[l] + bofX, jb.X + gxo[l] + k0);
#pragma unroll
            for (int l = 0; l < 4; l++)
                cp_async4(swa[l] + bofW, jb.W + gwo[l] + wstep);
            cp_commit();
            cp_wait1();
        } else {
            cp_wait0();
        }
        __syncthreads();
        int buf = t & 1;
#pragma unroll
        for (int k = 0; k < 16; k++) {
            float4 a0 = *reinterpret_cast<const float4*>(&sX[buf][k][m0]);
            float4 a1 = *reinterpret_cast<const float4*>(&sX[buf][k][m0 + 4]);
            float4 b  = *reinterpret_cast<const float4*>(&sW[buf][k][o0]);
            float av[8] = {a0.x, a0.y, a0.z, a0.w, a1.x, a1.y, a1.z, a1.w};
            float bv[4] = {b.x, b.y, b.z, b.w};
#pragma unroll
            for (int i = 0; i < 8; i++)
#pragma unroll
                for (int j = 0; j < 4; j++) acc[i][j] += av[i] * bv[j];
        }
        __syncthreads();
    }

#pragma unroll
    for (int i = 0; i < 8; i++) {
        int m = bm + m0 + i;
#pragma unroll
        for (int j = 0; j < 4; j++) {
            int o = bo + o0 + j;
            float v = acc[i][j] * jb.scale;
            if (jb.bias) v += jb.bias[o];
            if (jb.act == 1) v = v / (1.f + expf(-v));
            if (jb.out_mode == 0) {
                jb.C[(long long)m * jb.ldc + o] = v;
            } else {
                int cc = m / jb.nnodes;
                int n = m - cc * jb.nnodes;
                jb.C[(long long)n * 640 + 256 + o * 3 + cc] = v;
            }
        }
    }
}

__global__ void __launch_bounds__(256, 3)
gemm_multi(GemmJob j0, GemmJob j1, GemmJob j2) {
    int b = blockIdx.x;
    GemmJob jb = (b >= j2.off) ? j2 : (b >= j1.off) ? j1 : j0;
    int local = b - jb.off;
    gemm_body(jb, local % jb.gx, local / jb.gx);
}

// ---------------- helpers ----------------
__device__ __forceinline__ void red4(float* addr, float a, float b, float c, float d) {
    asm volatile("red.global.add.v4.f32 [%0], {%1,%2,%3,%4};"
                 :: "l"(addr), "f"(a), "f"(b), "f"(c), "f"(d) : "memory");
}
__device__ __forceinline__ float ssp_f(float x) {
    const float ln2 = 0.69314718055994531f;
    return fmaxf(x, 0.f) + log1pf(expf(-fabsf(x))) - ln2;
}

// ---------------- fused edge kernel (round-9 champion, inv32 folded) ----------------
#define ETILE 96
#define ETHREADS 768
#define OFF_WF1 0
#define OFF_WF2 (OFF_WF1 + 1024)
#define OFF_WC  (OFF_WF2 + 12288)
#define OFF_WL2 (OFF_WC + 2048)
#define OFF_EA  (OFF_WL2 + 12288)
#define OFF_NL  (OFF_EA + 96*33)
#define OFF_IP  (OFF_NL + 96*33)
#define OFF_EAT (OFF_IP + 96*65)
#define OFF_IPT (OFF_EAT + 32*96)
#define OFF_HF  (OFF_IPT + 64*96)
#define OFF_HL  (OFF_HF + 32*96)
#define OFF_SH  (OFF_HL + 32*96)
#define OFF_END (OFF_SH + 384)
#define EDGE_SMEM_BYTES (OFF_END*4 + 192*4)

__global__ void __launch_bounds__(ETHREADS, 1)
edge_kernel(const float* __restrict__ edge_attr,
            const float* __restrict__ edge_sh,
            const float* __restrict__ Wf1, const float* __restrict__ Wf2,
            const float* __restrict__ Wl1, const float* __restrict__ Wl2,
            int E, int N) {
    extern __shared__ float sm[];
    float* sWf1 = sm + OFF_WF1;
    float* sWf2 = sm + OFF_WF2;
    float* sWc  = sm + OFF_WC;
    float* sWl2 = sm + OFF_WL2;
    float* sea  = sm + OFF_EA;
    float* snl  = sm + OFF_NL;
    float* sip  = sm + OFF_IP;
    float* seaT = sm + OFF_EAT;
    float* sipT = sm + OFF_IPT;
    float* shfT = sm + OFF_HF;
    float* shlT = sm + OFF_HL;
    float* ssh  = sm + OFF_SH;
    int*   sidx = (int*)(sm + OFF_END);

    int tid = threadIdx.x;
    for (int i = tid; i < 1024;  i += ETHREADS) sWf1[i] = Wf1[i];
    for (int i = tid; i < 12288; i += ETHREADS) sWf2[i] = Wf2[i];
    for (int i = tid; i < 2048;  i += ETHREADS) sWc[i]  = Wl1[256 * 32 + i];
    for (int i = tid; i < 12288; i += ETHREADS) sWl2[i] = Wl2[i];

    const float c0 = 0.5f, c1 = 0.86602540378443865f;
    const float inv3 = 1.f / 3.f;
    const float invs32 = 0.17677669529663687f;
    const float invs320 = 0.05590169943749474f;
    const float invs3 = 0.57735026918962576f;

    int warp = tid >> 5, lane = tid & 31;
    int eb = warp * 4;

    int ntiles = (E + ETILE - 1) / ETILE;
    for (int tile = blockIdx.x; tile < ntiles; tile += gridDim.x) {
        int e0 = tile * ETILE;
        int cnt = min(ETILE, E - e0);
        __syncthreads();

        if (tid < ETILE) {
            int valid = tid < cnt;
            sidx[tid]         = valid ? g_ei[e0 + tid]     : 0;
            sidx[ETILE + tid] = valid ? g_ei[E + e0 + tid] : 0;
        }
        for (int i = tid; i < ETILE * 4; i += ETHREADS) {
            int t = i >> 2, q = i & 3;
            ssh[i] = (t < cnt) ? edge_sh[(size_t)(e0 + t) * 4 + q] : 0.f;
        }
        for (int i = tid; i < ETILE * 32; i += ETHREADS) {
            int t = i >> 5, q = i & 31;
            sea[t * 33 + q] = (t < cnt) ? edge_attr[(size_t)(e0 + t) * 32 + q] : 0.f;
        }
        __syncthreads();

        for (int i = tid; i < ETILE * 64; i += ETHREADS) {
            int t = i >> 6, u = i & 63;
            int d = sidx[t], s = sidx[ETILE + t];
            float acc = 0.f;
#pragma unroll
            for (int c = 0; c < 3; c++)
                acc += g_pre_v[((size_t)c * N + d) * 64 + u] *
                       g_pre_v[((size_t)c * N + s) * 64 + u];
            sip[t * 65 + u] = acc * inv3;
        }
        for (int i = tid; i < ETILE * 32; i += ETHREADS) {
            int t = i >> 5, j = i & 31;
            snl[t * 33 + j] = g_nl1[(size_t)sidx[t] * 32 + j];
        }
        __syncthreads();

        for (int i = tid; i < 32 * ETILE; i += ETHREADS) {
            int t = i % ETILE, q = i / ETILE;
            seaT[q * ETILE + t] = sea[t * 33 + q];
        }
        for (int i = tid; i < 64 * ETILE; i += ETHREADS) {
            int t = i % ETILE, u = i / ETILE;
            sipT[u * ETILE + t] = sip[t * 65 + u];
        }
        __syncthreads();

        if (warp < 6) {
            int idx = tid;
            int t0 = (idx % 24) * 4, j0 = (idx / 24) * 4;
            float acc[4][4];
#pragma unroll
            for (int a = 0; a < 4; a++)
#pragma unroll
                for (int b = 0; b < 4; b++) acc[a][b] = 0.f;
#pragma unroll 4
            for (int q = 0; q < 32; q++) {
                float4 hv = *reinterpret_cast<const float4*>(&seaT[q * ETILE + t0]);
                float4 wv = *reinterpret_cast<const float4*>(&sWf1[q * 32 + j0]);
                float h[4] = {hv.x, hv.y, hv.z, hv.w};
                float w[4] = {wv.x, wv.y, wv.z, wv.w};
#pragma unroll
                for (int a = 0; a < 4; a++)
#pragma unroll
                    for (int b = 0; b < 4; b++) acc[a][b] += h[a] * w[b];
            }
#pragma unroll
            for (int b = 0; b < 4; b++) {
                float4 o;
                o.x = ssp_f(acc[0][b] * invs32) * invs32;
                o.y = ssp_f(acc[1][b] * invs32) * invs32;
                o.z = ssp_f(acc[2][b] * invs32) * invs32;
                o.w = ssp_f(acc[3][b] * invs32) * invs32;
                *reinterpret_cast<float4*>(&shfT[(j0 + b) * ETILE + t0]) = o;
            }
        } else if (warp < 18) {
            int idx = tid - 192;
            int t0 = (idx % 48) * 2, j0 = (idx / 48) * 4;
            float acc[2][4];
#pragma unroll
            for (int a = 0; a < 2; a++)
#pragma unroll
                for (int b = 0; b < 4; b++) acc[a][b] = snl[(t0 + a) * 33 + j0 + b];
#pragma unroll 4
            for (int u = 0; u < 64; u++) {
                float2 hv = *reinterpret_cast<const float2*>(&sipT[u * ETILE + t0]);
                float4 wv = *reinterpret_cast<const float4*>(&sWc[u * 32 + j0]);
                float h[2] = {hv.x, hv.y};
                float w[4] = {wv.x, wv.y, wv.z, wv.w};
#pragma unroll
                for (int a = 0; a < 2; a++)
#pragma unroll
                    for (int b = 0; b < 4; b++) acc[a][b] += h[a] * w[b];
            }
#pragma unroll
            for (int b = 0; b < 4; b++) {
                float2 o;
                o.x = ssp_f(acc[0][b] * invs320) * invs32;
                o.y = ssp_f(acc[1][b] * invs320) * invs32;
                *reinterpret_cast<float2*>(&shlT[(j0 + b) * ETILE + t0]) = o;
            }
        }
        __syncthreads();

#pragma unroll 1
        for (int ob = 0; ob < 3; ob++) {
            int o0 = ob * 128 + lane * 4;
            float wf[4][4], wl[4][4];
#pragma unroll
            for (int a = 0; a < 4; a++)
#pragma unroll
                for (int b = 0; b < 4; b++) { wf[a][b] = 0.f; wl[a][b] = 0.f; }

#pragma unroll 2
            for (int j = 0; j < 32; j++) {
                float4 hf = *reinterpret_cast<const float4*>(&shfT[j * ETILE + eb]);
                float4 hl = *reinterpret_cast<const float4*>(&shlT[j * ETILE + eb]);
                float4 af = *reinterpret_cast<const float4*>(&sWf2[j * 384 + o0]);
                float4 al = *reinterpret_cast<const float4*>(&sWl2[j * 384 + o0]);
                float hfv[4] = {hf.x, hf.y, hf.z, hf.w};
                float hlv[4] = {hl.x, hl.y, hl.z, hl.w};
                float afv[4] = {af.x, af.y, af.z, af.w};
                float alv[4] = {al.x, al.y, al.z, al.w};
#pragma unroll
                for (int a = 0; a < 4; a++)
#pragma unroll
                    for (int b = 0; b < 4; b++) {
                        wf[a][b] += hfv[a] * afv[b];
                        wl[a][b] += hlv[a] * alv[b];
                    }
            }

#pragma unroll
            for (int a = 0; a < 4; a++) {
                int t = eb + a;
                if (t >= cnt) continue;
                int d = sidx[t], s = sidx[ETILE + t];
                float sh0 = ssh[t * 4 + 0];
                float w0 = wf[a][0] * wl[a][0];
                float w1 = wf[a][1] * wl[a][1];
                float w2 = wf[a][2] * wl[a][2];
                float w3 = wf[a][3] * wl[a][3];
                if (o0 < 128) {
                    float4 hs = *reinterpret_cast<const float4*>(&g_xs3[(size_t)s * 128 + o0]);
                    float k = c0 * sh0;
                    red4(&g_ns[(size_t)d * 192 + o0],
                         k * w0 * hs.x, k * w1 * hs.y, k * w2 * hs.z, k * w3 * hs.w);
                } else if (o0 < 256) {
                    int u0 = o0 - 128;
                    float4 hs = *reinterpret_cast<const float4*>(&g_xs3[(size_t)s * 128 + u0]);
                    float b0 = c1 * w0 * hs.x, b1 = c1 * w1 * hs.y;
                    float b2 = c1 * w2 * hs.z, b3 = c1 * w3 * hs.w;
#pragma unroll
                    for (int c = 0; c < 3; c++) {
                        float shc = ssh[t * 4 + 1 + c];
                        red4(&g_nv[((size_t)c * N + d) * 192 + u0],
                             b0 * shc, b1 * shc, b2 * shc, b3 * shc);
                    }
                } else if (o0 < 320) {
                    int u0 = o0 - 256;
                    float b0 = c1 * w0 * sh0, b1 = c1 * w1 * sh0;
                    float b2 = c1 * w2 * sh0, b3 = c1 * w3 * sh0;
#pragma unroll
                    for (int c = 0; c < 3; c++) {
                        float4 hv = *reinterpret_cast<const float4*>(
                            &g_xv3[((size_t)c * N + s) * 64 + u0]);
                        red4(&g_nv[((size_t)c * N + d) * 192 + 128 + u0],
                             b0 * hv.x, b1 * hv.y, b2 * hv.z, b3 * hv.w);
                    }
                } else {
                    int u0 = o0 - 320;
                    float4 hx = *reinterpret_cast<const float4*>(&g_xv3[((size_t)0 * N + s) * 64 + u0]);
                    float4 hy = *reinterpret_cast<const float4*>(&g_xv3[((size_t)1 * N + s) * 64 + u0]);
                    float4 hz = *reinterpret_cast<const float4*>(&g_xv3[((size_t)2 * N + s) * 64 + u0]);
                    float sh1 = ssh[t * 4 + 1], sh2v = ssh[t * 4 + 2], sh3 = ssh[t * 4 + 3];
                    float k = c0 * invs3;
                    red4(&g_ns[(size_t)d * 192 + 128 + u0],
                         k * w0 * (hx.x * sh1 + hy.x * sh2v + hz.x * sh3),
                         k * w1 * (hx.y * sh1 + hy.y * sh2v + hz.y * sh3),
                         k * w2 * (hx.z * sh1 + hy.z * sh2v + hz.z * sh3),
                         k * w3 * (hx.w * sh1 + hy.w * sh2v + hz.w * sh3));
                }
            }
        }
    }
}

// ---------------- launch ----------------
static GemmJob mkjob(const float* X, int ldx, const float* W, int ldw,
                     float* C, int ldc, int M, int K, int O,
                     float scale, const float* bias, int act,
                     int out_mode, int nnodes, int off) {
    GemmJob j;
    j.X = X; j.W = W; j.C = C; j.bias = bias;
    j.ldx = ldx; j.ldw = ldw; j.ldc = ldc;
    j.K = K; j.scale = scale; j.act = act;
    j.out_mode = out_mode; j.nnodes = nnodes;
    j.gx = O / 64; j.gy = M / 128; j.off = off;
    return j;
}

extern "C" void kernel_launch(void* const* d_in, const int* in_sizes, int n_in,
                              void* d_out, int out_size) {
    const float* x      = (const float*)d_in[0];
    const int*   ei_raw = (const int*)d_in[1];
    const float* ea     = (const float*)d_in[2];
    const float* esh    = (const float*)d_in[3];
    const float* Wpre_s = (const float*)d_in[4];
    const float* bpre_s = (const float*)d_in[5];
    const float* Wpre_v = (const float*)d_in[6];
    const float* Wg1    = (const float*)d_in[7];
    const float* bg1    = (const float*)d_in[8];
    const float* Wg2    = (const float*)d_in[9];
    const float* bg2    = (const float*)d_in[10];
    const float* Wn_s   = (const float*)d_in[11];
    const float* bn_s   = (const float*)d_in[12];
    const float* Wn_v   = (const float*)d_in[13];
    const float* Wf1    = (const float*)d_in[14];
    const float* Wf2    = (const float*)d_in[15];
    const float* Wl1    = (const float*)d_in[16];
    const float* Wl2    = (const float*)d_in[17];
    const float* Wo_s   = (const float*)d_in[18];
    const float* bo_s   = (const float*)d_in[19];
    const float* Wo_v   = (const float*)d_in[20];

    int N = in_sizes[0] / 320;
    int E = in_sizes[1] / 2;
    float* out = (float*)d_out;

    float *p_xvT, *p_f0, *p_pre_s, *p_pre_v, *p_h1, *p_g, *p_xv2T, *p_xs3, *p_ns, *p_nv, *p_xv3;
    cudaGetSymbolAddress((void**)&p_xvT,  g_xvT);
    cudaGetSymbolAddress((void**)&p_f0,   g_f0);
    cudaGetSymbolAddress((void**)&p_pre_s,g_pre_s);
    cudaGetSymbolAddress((void**)&p_pre_v,g_pre_v);
    cudaGetSymbolAddress((void**)&p_h1,   g_h1);
    cudaGetSymbolAddress((void**)&p_g,    g_g);
    cudaGetSymbolAddress((void**)&p_xv2T, g_xv2T);
    cudaGetSymbolAddress((void**)&p_xs3,  g_xs3);
    cudaGetSymbolAddress((void**)&p_ns,   g_ns);
    cudaGetSymbolAddress((void**)&p_nv,   g_nv);
    cudaGetSymbolAddress((void**)&p_xv3,  g_xv3);

    const float s128 = 0.08838834764831845f;
    const float s64  = 0.125f;
    const float s192 = 0.07216878364870323f;

    convert_kernel<<<512, 256>>>(ei_raw, 2 * E);
    prep_kernel<<<2048, 256>>>(x, N);

    // Phase A: pre_s | pre_v | h1
    {
        GemmJob jA = mkjob(x, 320, Wpre_s, 128, p_pre_s, 128, N, 128, 128, s128, bpre_s, 0, 0, 0, 0);
        int c0 = jA.gx * jA.gy;
        GemmJob jB = mkjob(p_xvT, 64, Wpre_v, 64, p_pre_v, 64, 3 * N, 64, 64, s64, nullptr, 0, 0, 0, c0);
        int c1 = c0 + jB.gx * jB.gy;
        GemmJob jC = mkjob(p_f0, 192, Wg1, 192, p_h1, 192, N, 192, 192, 1.f, bg1, 1, 0, 0, c1);
        int total = c1 + jC.gx * jC.gy;
        gemm_multi<<<total, 256>>>(jA, jB, jC);
    }
    // g = h1 @ Wg2 + bg2
    {
        GemmJob jA = mkjob(p_h1, 192, Wg2, 192, p_g, 192, N, 192, 192, 1.f, bg2, 0, 0, 0, 0);
        int total = jA.gx * jA.gy;
        GemmJob jX = jA; jX.off = total;
        gemm_multi<<<total, 256>>>(jA, jX, jX);
    }

    gate_kernel<<<2048, 256>>>(N);
    wsum_kernel<<<16, 256>>>(Wl1);
    nl1_kernel<<<(N + 7) / 8, 256>>>(N);

    // Phase B: xs3 (K=128) | xv3
    {
        GemmJob jA = mkjob(p_g, 192, Wn_s, 128, p_xs3, 128, N, 128, 128, s128, bn_s, 0, 0, 0, 0);
        int c0 = jA.gx * jA.gy;
        GemmJob jB = mkjob(p_xv2T, 64, Wn_v, 64, p_xv3, 64, 3 * N, 64, 64, s64, nullptr, 0, 0, 0, c0);
        int total = c0 + jB.gx * jB.gy;
        GemmJob jX = jB; jX.off = total;
        gemm_multi<<<total, 256>>>(jA, jB, jX);
    }

    zero_kernel<<<2048, 256>>>(N);

    cudaFuncSetAttribute(edge_kernel, cudaFuncAttributeMaxDynamicSharedMemorySize,
                         EDGE_SMEM_BYTES);
    edge_kernel<<<148, ETHREADS, EDGE_SMEM_BYTES>>>(ea, esh, Wf1, Wf2, Wl1, Wl2, E, N);

    // Phase C: outs | outv
    {
        GemmJob jA = mkjob(p_ns, 192, Wo_s, 256, out, 640, N, 192, 256, s192, bo_s, 0, 0, 0, 0);
        int c0 = jA.gx * jA.gy;
        GemmJob jB = mkjob(p_nv, 192, Wo_v, 128, out, 0, 3 * N, 192, 128, s192, nullptr, 0, 1, N, c0);
        int total = c0 + jB.gx * jB.gy;
        GemmJob jX = jB; jX.off = total;
        gemm_multi<<<total, 256>>>(jA, jB, jX);
    }
}